// round 13
// baseline (speedup 1.0000x reference)
#include <cuda_runtime.h>
#include <cuda_bf16.h>
#include <math.h>
#include <stdint.h>

#define Bn 2
#define Ln 1024
#define Dn 1024
#define Hn 16
#define HDn 64
#define NT 2048       // Bn*Ln tokens
#define NCn 16        // chunks per sequence (Ln/64)
#define BHn 32        // Bn*Hn

// ---------------- scratch (static device globals; no allocation allowed) ---
__device__ float g_q[NT * Dn];
__device__ float g_k[NT * Dn];
__device__ float g_v[NT * Dn];
__device__ float g_beta[NT * Hn];
__device__ float g_sdelta[BHn * NCn * HDn * HDn];
__device__ float g_sprefix[BHn * NCn * HDn * HDn];
// bf16 hi/lo operands for tensor-core GEMMs
__device__ __nv_bfloat16 g_xh[NT * Dn], g_xl[NT * Dn];
__device__ __nv_bfloat16 g_wth[4 * Dn * Dn], g_wtl[4 * Dn * Dn];  // W^T [N][K], 4 mats
__device__ __nv_bfloat16 g_ah[NT * Dn], g_al[NT * Dn];            // attn hi/lo

// =================== helpers ===============================================
__device__ __forceinline__ uint32_t smem_u32(const void* p) {
    uint32_t a;
    asm("{ .reg .u64 t; cvta.to.shared.u64 t, %1; cvt.u32.u64 %0, t; }"
        : "=r"(a) : "l"(p));
    return a;
}
__device__ __forceinline__ void cp_async16(uint32_t saddr, const void* gptr) {
    asm volatile("cp.async.cg.shared.global [%0], [%1], 16;"
                 :: "r"(saddr), "l"(gptr) : "memory");
}
#define CP_COMMIT() asm volatile("cp.async.commit_group;" ::: "memory")
#define CP_WAIT0()  asm volatile("cp.async.wait_group 0;" ::: "memory")
#define CP_WAIT1()  asm volatile("cp.async.wait_group 1;" ::: "memory")

__device__ __forceinline__ void ldsm_x4(uint32_t* r, uint32_t addr) {
    asm volatile("ldmatrix.sync.aligned.m8n8.x4.shared.b16 {%0,%1,%2,%3}, [%4];"
                 : "=r"(r[0]), "=r"(r[1]), "=r"(r[2]), "=r"(r[3]) : "r"(addr));
}
__device__ __forceinline__ void ldsm_x2(uint32_t* r, uint32_t addr) {
    asm volatile("ldmatrix.sync.aligned.m8n8.x2.shared.b16 {%0,%1}, [%2];"
                 : "=r"(r[0]), "=r"(r[1]) : "r"(addr));
}

// mma.sync m16n8k16 bf16 -> fp32 (HMMA path; plain compute_80+ PTX)
__device__ __forceinline__ void mma16816(float* c, const uint32_t* a, const uint32_t* b) {
    asm volatile(
        "mma.sync.aligned.m16n8k16.row.col.f32.bf16.bf16.f32 "
        "{%0,%1,%2,%3}, {%4,%5,%6,%7}, {%8,%9}, {%0,%1,%2,%3};"
        : "+f"(c[0]), "+f"(c[1]), "+f"(c[2]), "+f"(c[3])
        : "r"(a[0]), "r"(a[1]), "r"(a[2]), "r"(a[3]), "r"(b[0]), "r"(b[1]));
}

__device__ __forceinline__ void split_hl(float v, __nv_bfloat16& h, __nv_bfloat16& l) {
    h = __float2bfloat16(v);
    l = __float2bfloat16(v - __bfloat162float(h));
}

// ---------------- operand conversion kernels -------------------------------
__global__ void __launch_bounds__(256) convert_x_kernel(const float* __restrict__ x) {
    size_t i = ((size_t)blockIdx.x * 256 + threadIdx.x) * 4;
    float4 v = *(const float4*)(x + i);
    float f[4] = {v.x, v.y, v.z, v.w};
    __nv_bfloat16 h[4], l[4];
#pragma unroll
    for (int j = 0; j < 4; j++) split_hl(f[j], h[j], l[j]);
    __nv_bfloat162 h01, h23, l01, l23;
    h01.x = h[0]; h01.y = h[1]; h23.x = h[2]; h23.y = h[3];
    l01.x = l[0]; l01.y = l[1]; l23.x = l[2]; l23.y = l[3];
    *(__nv_bfloat162*)(g_xh + i)     = h01;
    *(__nv_bfloat162*)(g_xh + i + 2) = h23;
    *(__nv_bfloat162*)(g_xl + i)     = l01;
    *(__nv_bfloat162*)(g_xl + i + 2) = l23;
}

// transpose W[K][N] -> Wt[N][K], split hi/lo
__global__ void __launch_bounds__(256) convert_w_kernel(
    const float* __restrict__ Wq, const float* __restrict__ Wk,
    const float* __restrict__ Wv, const float* __restrict__ Wo) {
    __shared__ float t[32][33];
    const float* W = (blockIdx.z == 0) ? Wq : (blockIdx.z == 1) ? Wk
                   : (blockIdx.z == 2) ? Wv : Wo;
    int n0 = blockIdx.x * 32, k0 = blockIdx.y * 32;
    int tx = threadIdx.x, ty = threadIdx.y;  // block (32,8)
#pragma unroll
    for (int r = 0; r < 4; r++)
        t[ty + 8 * r][tx] = W[(size_t)(k0 + ty + 8 * r) * Dn + n0 + tx];
    __syncthreads();
    size_t ob = (size_t)blockIdx.z * Dn * Dn;
#pragma unroll
    for (int r = 0; r < 4; r++) {
        float v = t[tx][ty + 8 * r];
        size_t o = ob + (size_t)(n0 + ty + 8 * r) * Dn + k0 + tx;
        __nv_bfloat16 h, l;
        split_hl(v, h, l);
        g_wth[o] = h;
        g_wtl[o] = l;
    }
}

// ---------------- bf16 3-term MMA GEMM: C = A @ Wt^T -----------------------
// 128x64 CTA tile, BK=32, 8 warps 2(M)x4(N), warp tile 64x16, 3-stage pipe.
#define KPAD 40                        // bf16 elems per smem row (32 + 8 pad)
#define TA_E (128 * KPAD)              // A tile elems (one of hi/lo)
#define TB_E (64 * KPAD)               // B tile elems (one of hi/lo)
#define STG_E (2 * TA_E + 2 * TB_E)    // stage elems = 15360
#define MM_SMEM_B (3 * STG_E * 2)      // 92160 bytes (3 stages)

__device__ __forceinline__ void mm_issue_stage(
    uint32_t st, int kc, int tid,
    const __nv_bfloat16* Ah, const __nv_bfloat16* Al,
    const __nv_bfloat16* Bh, const __nv_bfloat16* Bl) {
    // A hi/lo: 128 rows x 4 segs, paired addresses (ternary-free)
#pragma unroll
    for (int i = 0; i < 2; i++) {
        int idx = tid + i * 256;              // 0..511
        int rr = idx >> 2, seg = idx & 3;
        size_t go = (size_t)rr * Dn + kc * 32 + seg * 8;
        uint32_t so = (uint32_t)(rr * KPAD + seg * 8) * 2;
        cp_async16(st + so,            Ah + go);
        cp_async16(st + TA_E * 2 + so, Al + go);
    }
    // B hi/lo: 64 rows x 4 segs
    {
        int rr = tid >> 2, seg = tid & 3;
        size_t go = (size_t)rr * Dn + kc * 32 + seg * 8;
        uint32_t so = (uint32_t)(rr * KPAD + seg * 8) * 2;
        cp_async16(st + 2 * TA_E * 2 + so,            Bh + go);
        cp_async16(st + (2 * TA_E + TB_E) * 2 + so,   Bl + go);
    }
    CP_COMMIT();
}

__device__ __forceinline__ void mm_gemm_body(
    const __nv_bfloat16* __restrict__ Agh, const __nv_bfloat16* __restrict__ Agl,
    const __nv_bfloat16* __restrict__ Bgh, const __nv_bfloat16* __restrict__ Bgl,
    float* __restrict__ C) {
    extern __shared__ __nv_bfloat16 sm[];
    const uint32_t sbase = smem_u32(sm);
    const int tid = threadIdx.x, lane = tid & 31, wid = tid >> 5;
    const int wm = wid & 1, wn = wid >> 1;
    const int m0 = blockIdx.y * 128, n0 = blockIdx.x * 64;

    const __nv_bfloat16* Ah = Agh + (size_t)m0 * Dn;
    const __nv_bfloat16* Al = Agl + (size_t)m0 * Dn;
    const __nv_bfloat16* Bh = Bgh + (size_t)n0 * Dn;
    const __nv_bfloat16* Bl = Bgl + (size_t)n0 * Dn;

    float c[4][2][4];
#pragma unroll
    for (int i = 0; i < 4; i++)
#pragma unroll
        for (int j = 0; j < 2; j++)
#pragma unroll
            for (int r = 0; r < 4; r++) c[i][j][r] = 0.f;

    // prologue: 2 stages in flight
    mm_issue_stage(sbase,                          0, tid, Ah, Al, Bh, Bl);
    mm_issue_stage(sbase + (uint32_t)(STG_E * 2),  1, tid, Ah, Al, Bh, Bl);

    // ldmatrix lane addressing (bf16 elements)
    const int a_r = (lane & 7) + ((lane >> 3) & 1) * 8;  // row in 16-row tile
    const int a_c = (lane >> 4) * 8;                     // k col-half 0/8
    const int b_r = lane & 7;                            // row in 8-row tile
    const int b_c = ((lane >> 3) & 1) * 8;               // k col-half (lanes 0-15)
    // epilogue addressing
    const int g4 = lane >> 2;
    const int cpair = (lane & 3) * 2;

    for (int kc = 0; kc < 32; kc++) {
        if (kc + 1 < 32) { CP_WAIT1(); } else { CP_WAIT0(); }
        __syncthreads();
        if (kc + 2 < 32)
            mm_issue_stage(sbase + (uint32_t)((kc + 2) % 3) * (STG_E * 2),
                           kc + 2, tid, Ah, Al, Bh, Bl);

        const uint32_t st = sbase + (uint32_t)(kc % 3) * (STG_E * 2);
        const uint32_t stAh = st;
        const uint32_t stAl = st + TA_E * 2;
        const uint32_t stBh = st + 2 * TA_E * 2;
        const uint32_t stBl = st + (2 * TA_E + TB_E) * 2;

#pragma unroll
        for (int ks = 0; ks < 2; ks++) {
            const int kk = ks * 16;
            uint32_t bh[2][2], bl[2][2];
#pragma unroll
            for (int nf = 0; nf < 2; nf++) {
                uint32_t bo = (uint32_t)((wn * 16 + nf * 8 + b_r) * KPAD + kk + b_c) * 2;
                ldsm_x2(bh[nf], stBh + bo);
                ldsm_x2(bl[nf], stBl + bo);
            }
#pragma unroll
            for (int mf = 0; mf < 4; mf++) {
                uint32_t ao = (uint32_t)((wm * 64 + mf * 16 + a_r) * KPAD + kk + a_c) * 2;
                uint32_t ah[4], al[4];
                ldsm_x4(ah, stAh + ao);
                ldsm_x4(al, stAl + ao);
#pragma unroll
                for (int nf = 0; nf < 2; nf++) {
                    mma16816(c[mf][nf], ah, bh[nf]);
                    mma16816(c[mf][nf], ah, bl[nf]);
                    mma16816(c[mf][nf], al, bh[nf]);
                }
            }
        }
    }

    // epilogue: write fp32 C
#pragma unroll
    for (int mf = 0; mf < 4; mf++) {
        int r = m0 + wm * 64 + mf * 16 + g4;
#pragma unroll
        for (int nf = 0; nf < 2; nf++) {
            int cc = n0 + wn * 16 + nf * 8 + cpair;
            *(float2*)(C + (size_t)r * Dn + cc)       = make_float2(c[mf][nf][0], c[mf][nf][1]);
            *(float2*)(C + (size_t)(r + 8) * Dn + cc) = make_float2(c[mf][nf][2], c[mf][nf][3]);
        }
    }
}

__global__ void __launch_bounds__(256, 2) mm_qkv_kernel() {
    const size_t wo = (size_t)blockIdx.z * Dn * Dn;
    float* C = (blockIdx.z == 0) ? g_q : (blockIdx.z == 1) ? g_k : g_v;
    mm_gemm_body(g_xh, g_xl, g_wth + wo, g_wtl + wo, C);
}
__global__ void __launch_bounds__(256, 2) mm_out_kernel(float* __restrict__ out) {
    mm_gemm_body(g_ah, g_al, g_wth + 3ull * Dn * Dn, g_wtl + 3ull * Dn * Dn, out);
}

// ---------------- beta = sigmoid(x @ Wb + bb) ------------------------------
// 4 tokens/block, K split 4-ways, 512 blocks (fills the chip).
__global__ void __launch_bounds__(256) beta_kernel(const float* __restrict__ x,
                                                   const float* __restrict__ Wb,
                                                   const float* __restrict__ bbias) {
    __shared__ float sred[8][16];
    const int tid = threadIdx.x;
    const int h = tid & 15, q = (tid >> 4) & 3, t = tid >> 6;
    const int tok = blockIdx.x * 4 + t;
    const float* xr = x + (size_t)tok * Dn + q * 256;
    const float* wr = Wb + (size_t)(q * 256) * Hn + h;
    float a0 = 0.f, a1 = 0.f, a2 = 0.f, a3 = 0.f;
#pragma unroll 4
    for (int k = 0; k < 256; k += 4) {
        a0 += xr[k + 0] * wr[(size_t)(k + 0) * Hn];
        a1 += xr[k + 1] * wr[(size_t)(k + 1) * Hn];
        a2 += xr[k + 2] * wr[(size_t)(k + 2) * Hn];
        a3 += xr[k + 3] * wr[(size_t)(k + 3) * Hn];
    }
    float s = (a0 + a1) + (a2 + a3);
    s += __shfl_xor_sync(0xffffffffu, s, 16);
    const int wd = tid >> 5;
    if ((tid & 31) < 16) sred[wd][h] = s;
    __syncthreads();
    if (tid < 64) {
        int tt = tid >> 4, hh = tid & 15;
        float tot = sred[2 * tt][hh] + sred[2 * tt + 1][hh] + bbias[hh];
        g_beta[(size_t)(blockIdx.x * 4 + tt) * Hn + hh] = 1.f / (1.f + expf(-tot));
    }
}

// ---------------- per-chunk state delta: dS = (beta * k/||k||)^T @ v -------
// (l2norm fused: row norms computed during load via 16-lane shuffle)
__global__ void __launch_bounds__(256) chunk_delta_kernel() {
    __shared__ float skb[64 * 64];
    __shared__ float sv[64 * 64];
    __shared__ float sbeta[64];
    __shared__ float snorm[64];
    const int c = blockIdx.x, bh = blockIdx.y;
    const int b = bh >> 4, h = bh & 15;
    const int tid = threadIdx.x;
    const int tx = tid & 15, ty = tid >> 4;
    const size_t rowbase = (size_t)b * Ln + c * 64;

#pragma unroll
    for (int r = 0; r < 4; r++) {
        int t = r * 16 + (tid >> 4);
        int e4 = (tid & 15) * 4;
        size_t g = (rowbase + t) * Dn + h * 64 + e4;
        float4 kv = *(const float4*)&g_k[g];
        *(float4*)&skb[t * 64 + e4] = kv;
        *(float4*)&sv[t * 64 + e4] = *(const float4*)&g_v[g];
        float ss = kv.x * kv.x + kv.y * kv.y + kv.z * kv.z + kv.w * kv.w;
        ss += __shfl_xor_sync(0xffffffffu, ss, 1);
        ss += __shfl_xor_sync(0xffffffffu, ss, 2);
        ss += __shfl_xor_sync(0xffffffffu, ss, 4);
        ss += __shfl_xor_sync(0xffffffffu, ss, 8);
        if ((tid & 15) == 0) snorm[t] = ss;
    }
    __syncthreads();
    if (tid < 64)
        sbeta[tid] = g_beta[(rowbase + tid) * Hn + h] /
                     fmaxf(sqrtf(snorm[tid]), 1e-12f);
    __syncthreads();

    float acc[4][4];
#pragma unroll
    for (int i = 0; i < 4; i++)
#pragma unroll
        for (int j = 0; j < 4; j++) acc[i][j] = 0.f;
#pragma unroll 8
    for (int t = 0; t < 64; t++) {
        float4 a = *(const float4*)&skb[t * 64 + ty * 4];
        float s = sbeta[t];
        float4 b4 = *(const float4*)&sv[t * 64 + tx * 4];
        const float af[4] = {a.x * s, a.y * s, a.z * s, a.w * s};
        const float bf[4] = {b4.x, b4.y, b4.z, b4.w};
#pragma unroll
        for (int i = 0; i < 4; i++)
#pragma unroll
            for (int j = 0; j < 4; j++) acc[i][j] += af[i] * bf[j];
    }
    const size_t sbase = ((size_t)bh * NCn + c) * 4096;
#pragma unroll
    for (int i = 0; i < 4; i++)
        *(float4*)&g_sdelta[sbase + (ty * 4 + i) * 64 + tx * 4] =
            make_float4(acc[i][0], acc[i][1], acc[i][2], acc[i][3]);
}

// ---------------- exclusive prefix over 16 chunk states per (b,h) ----------
__global__ void __launch_bounds__(256) prefix_kernel() {
    const int bh = blockIdx.x;
    const int off = blockIdx.y * 1024 + threadIdx.x * 4;
    float4 acc = make_float4(0.f, 0.f, 0.f, 0.f);
    for (int c = 0; c < NCn; c++) {
        size_t base = ((size_t)bh * NCn + c) * 4096 + off;
        *(float4*)&g_sprefix[base] = acc;
        float4 d = *(const float4*)&g_sdelta[base];
        acc.x += d.x; acc.y += d.y; acc.z += d.z; acc.w += d.w;
    }
}

// ---------------- per-chunk output ----------------------------------------
// out = qn @ S_prev + tril(qn kn^T) * beta @ v ; q,k norms fused in.
__global__ void __launch_bounds__(256) chunk_out_kernel() {
    extern __shared__ float smf[];
    float* sqT = smf;             // [64][65] transposed raw q
    float* sX  = smf + 4160;      // multi-use
    float* sA  = smf + 8320;      // [64][64] A^T
    float* sbeta = smf + 12416;   // [64]
    float* sqn = smf + 12480;     // [64] ||q||^2
    float* skn = smf + 12544;     // [64] ||k||^2
    const int c = blockIdx.x, bh = blockIdx.y;
    const int b = bh >> 4, h = bh & 15;
    const int tid = threadIdx.x;
    const int tx = tid & 15, ty = tid >> 4;
    const size_t rowbase = (size_t)b * Ln + c * 64;
    const size_t sbase = ((size_t)bh * NCn + c) * 4096;

    if (tid < 64) sbeta[tid] = g_beta[(rowbase + tid) * Hn + h];
    // load q transposed + row sumsq
#pragma unroll
    for (int r = 0; r < 4; r++) {
        int t = r * 16 + (tid >> 4);
        int d4 = (tid & 15) * 4;
        float4 qv = *(const float4*)&g_q[(rowbase + t) * Dn + h * 64 + d4];
        sqT[(d4 + 0) * 65 + t] = qv.x;
        sqT[(d4 + 1) * 65 + t] = qv.y;
        sqT[(d4 + 2) * 65 + t] = qv.z;
        sqT[(d4 + 3) * 65 + t] = qv.w;
        float ss = qv.x * qv.x + qv.y * qv.y + qv.z * qv.z + qv.w * qv.w;
        ss += __shfl_xor_sync(0xffffffffu, ss, 1);
        ss += __shfl_xor_sync(0xffffffffu, ss, 2);
        ss += __shfl_xor_sync(0xffffffffu, ss, 4);
        ss += __shfl_xor_sync(0xffffffffu, ss, 8);
        if ((tid & 15) == 0) sqn[t] = ss;
    }
#pragma unroll
    for (int r = 0; r < 4; r++) {
        int idx = r * 1024 + tid * 4;
        *(float4*)&sX[idx] = *(const float4*)&g_sprefix[sbase + idx];
    }
    __syncthreads();

    float acc[4][4];
#pragma unroll
    for (int i = 0; i < 4; i++)
#pragma unroll
        for (int j = 0; j < 4; j++) acc[i][j] = 0.f;

    // phase 1: acc = q_raw @ S_prev  (1/||q|| applied at final write)
#pragma unroll 8
    for (int d = 0; d < 64; d++) {
        float a0 = sqT[d * 65 + ty * 4 + 0];
        float a1 = sqT[d * 65 + ty * 4 + 1];
        float a2v = sqT[d * 65 + ty * 4 + 2];
        float a3 = sqT[d * 65 + ty * 4 + 3];
        float4 bv = *(const float4*)&sX[d * 64 + tx * 4];
        acc[0][0] += a0 * bv.x; acc[0][1] += a0 * bv.y; acc[0][2] += a0 * bv.z; acc[0][3] += a0 * bv.w;
        acc[1][0] += a1 * bv.x; acc[1][1] += a1 * bv.y; acc[1][2] += a1 * bv.z; acc[1][3] += a1 * bv.w;
        acc[2][0] += a2v * bv.x; acc[2][1] += a2v * bv.y; acc[2][2] += a2v * bv.z; acc[2][3] += a2v * bv.w;
        acc[3][0] += a3 * bv.x; acc[3][1] += a3 * bv.y; acc[3][2] += a3 * bv.z; acc[3][3] += a3 * bv.w;
    }
    __syncthreads();
    // load k transposed into sX + row sumsq
#pragma unroll
    for (int r = 0; r < 4; r++) {
        int t = r * 16 + (tid >> 4);
        int d4 = (tid & 15) * 4;
        float4 kv = *(const float4*)&g_k[(rowbase + t) * Dn + h * 64 + d4];
        sX[(d4 + 0) * 65 + t] = kv.x;
        sX[(d4 + 1) * 65 + t] = kv.y;
        sX[(d4 + 2) * 65 + t] = kv.z;
        sX[(d4 + 3) * 65 + t] = kv.w;
        float ss = kv.x * kv.x + kv.y * kv.y + kv.z * kv.z + kv.w * kv.w;
        ss += __shfl_xor_sync(0xffffffffu, ss, 1);
        ss += __shfl_xor_sync(0xffffffffu, ss, 2);
        ss += __shfl_xor_sync(0xffffffffu, ss, 4);
        ss += __shfl_xor_sync(0xffffffffu, ss, 8);
        if ((tid & 15) == 0) skn[t] = ss;
    }
    __syncthreads();

    // phase 2: A[t][s] = q_t.k_s (raw); mask s<=t; scale beta[s]/||k_s||; store A^T
    float a2[4][4];
#pragma unroll
    for (int i = 0; i < 4; i++)
#pragma unroll
        for (int j = 0; j < 4; j++) a2[i][j] = 0.f;
#pragma unroll 8
    for (int d = 0; d < 64; d++) {
        float af[4], bf[4];
#pragma unroll
        for (int i = 0; i < 4; i++) af[i] = sqT[d * 65 + ty * 4 + i];
#pragma unroll
        for (int j = 0; j < 4; j++) bf[j] = sX[d * 65 + tx * 4 + j];
#pragma unroll
        for (int i = 0; i < 4; i++)
#pragma unroll
            for (int j = 0; j < 4; j++) a2[i][j] += af[i] * bf[j];
    }
#pragma unroll
    for (int j = 0; j < 4; j++) {
        int s = tx * 4 + j;
        float bscale = sbeta[s] / fmaxf(sqrtf(skn[s]), 1e-12f);
        float4 v4;
        v4.x = (s <= ty * 4 + 0) ? a2[0][j] * bscale : 0.f;
        v4.y = (s <= ty * 4 + 1) ? a2[1][j] * bscale : 0.f;
        v4.z = (s <= ty * 4 + 2) ? a2[2][j] * bscale : 0.f;
        v4.w = (s <= ty * 4 + 3) ? a2[3][j] * bscale : 0.f;
        *(float4*)&sA[s * 64 + ty * 4] = v4;
    }
    __syncthreads();
#pragma unroll
    for (int r = 0; r < 4; r++) {
        int t = r * 16 + (tid >> 4);
        int e4 = (tid & 15) * 4;
        *(float4*)&sX[t * 64 + e4] =
            *(const float4*)&g_v[(rowbase + t) * Dn + h * 64 + e4];
    }
    __syncthreads();

    // phase 3: acc += A @ v
#pragma unroll 8
    for (int s = 0; s < 64; s++) {
        float4 av = *(const float4*)&sA[s * 64 + ty * 4];
        float4 bv = *(const float4*)&sX[s * 64 + tx * 4];
        const float af[4] = {av.x, av.y, av.z, av.w};
        const float bf[4] = {bv.x, bv.y, bv.z, bv.w};
#pragma unroll
        for (int i = 0; i < 4; i++)
#pragma unroll
            for (int j = 0; j < 4; j++) acc[i][j] += af[i] * bf[j];
    }
    // write attn (scaled by 1/||q_t||) as bf16 hi/lo
#pragma unroll
    for (int i = 0; i < 4; i++) {
        int t = ty * 4 + i;
        float inq = 1.f / fmaxf(sqrtf(sqn[t]), 1e-12f);
        size_t base = (rowbase + t) * Dn + h * 64 + tx * 4;
        __nv_bfloat16 hh[4], ll[4];
#pragma unroll
        for (int j = 0; j < 4; j++) split_hl(acc[i][j] * inq, hh[j], ll[j]);
        __nv_bfloat162 h01, h23, l01, l23;
        h01.x = hh[0]; h01.y = hh[1]; h23.x = hh[2]; h23.y = hh[3];
        l01.x = ll[0]; l01.y = ll[1]; l23.x = ll[2]; l23.y = ll[3];
        *(__nv_bfloat162*)(g_ah + base)     = h01;
        *(__nv_bfloat162*)(g_ah + base + 2) = h23;
        *(__nv_bfloat162*)(g_al + base)     = l01;
        *(__nv_bfloat162*)(g_al + base + 2) = l23;
    }
}

// ---------------------------------------------------------------------------
extern "C" void kernel_launch(void* const* d_in, const int* in_sizes, int n_in,
                              void* d_out, int out_size) {
    const float* x  = (const float*)d_in[0];
    const float* Wq = (const float*)d_in[1];
    const float* Wk = (const float*)d_in[2];
    const float* Wv = (const float*)d_in[3];
    const float* Wo = (const float*)d_in[4];
    const float* Wb = (const float*)d_in[5];
    const float* bb = (const float*)d_in[6];
    float* out = (float*)d_out;

    cudaFuncSetAttribute(mm_qkv_kernel,
                         cudaFuncAttributeMaxDynamicSharedMemorySize, MM_SMEM_B);
    cudaFuncSetAttribute(mm_out_kernel,
                         cudaFuncAttributeMaxDynamicSharedMemorySize, MM_SMEM_B);
    cudaFuncSetAttribute(chunk_out_kernel,
                         cudaFuncAttributeMaxDynamicSharedMemorySize, 12608 * 4);

    // operand conversion: x -> bf16 hi/lo, W -> W^T bf16 hi/lo
    convert_x_kernel<<<NT * Dn / 1024, 256>>>(x);
    convert_w_kernel<<<dim3(32, 32, 4), dim3(32, 8)>>>(Wq, Wk, Wv, Wo);
    // gates (launched before mm_qkv so mm_qkv lands in the ncu capture slot)
    beta_kernel<<<NT / 4, 256>>>(x, Wb, bb);
    // q,k,v projections on tensor cores (3-term bf16 hi/lo; 128x64 tiles)
    mm_qkv_kernel<<<dim3(Dn / 64, NT / 128, 3), 256, MM_SMEM_B>>>();
    // chunk-local state deltas (k-norm fused)
    chunk_delta_kernel<<<dim3(NCn, BHn), 256>>>();
    // exclusive prefix over chunk states
    prefix_kernel<<<dim3(BHn, 4), 256>>>();
    // per-chunk outputs (q/k-norm fused; writes attn bf16 hi/lo)
    chunk_out_kernel<<<dim3(NCn, BHn), 256, 12608 * 4>>>();
    // final projection on tensor cores (256 CTAs = one full wave)
    mm_out_kernel<<<dim3(Dn / 64, NT / 128), 256, MM_SMEM_B>>>(out);
}

// round 15
// speedup vs baseline: 1.0611x; 1.0611x over previous
#include <cuda_runtime.h>
#include <cuda_bf16.h>
#include <math.h>
#include <stdint.h>

#define Bn 2
#define Ln 1024
#define Dn 1024
#define Hn 16
#define HDn 64
#define NT 2048       // Bn*Ln tokens
#define NCn 16        // chunks per sequence (Ln/64)
#define BHn 32        // Bn*Hn

// ---------------- scratch (static device globals; no allocation allowed) ---
__device__ float g_q[NT * Dn];
__device__ float g_k[NT * Dn];
__device__ float g_v[NT * Dn];
__device__ float g_beta[NT * Hn];
__device__ float g_sdelta[BHn * NCn * HDn * HDn];
__device__ float g_sprefix[BHn * NCn * HDn * HDn];
// bf16 hi/lo operands for tensor-core GEMMs
__device__ __nv_bfloat16 g_xh[NT * Dn], g_xl[NT * Dn];
__device__ __nv_bfloat16 g_wth[4 * Dn * Dn], g_wtl[4 * Dn * Dn];  // W^T [N][K], 4 mats
__device__ __nv_bfloat16 g_ah[NT * Dn], g_al[NT * Dn];            // attn hi/lo

// =================== helpers ===============================================
__device__ __forceinline__ uint32_t smem_u32(const void* p) {
    uint32_t a;
    asm("{ .reg .u64 t; cvta.to.shared.u64 t, %1; cvt.u32.u64 %0, t; }"
        : "=r"(a) : "l"(p));
    return a;
}
__device__ __forceinline__ void cp_async16(uint32_t saddr, const void* gptr) {
    asm volatile("cp.async.cg.shared.global [%0], [%1], 16;"
                 :: "r"(saddr), "l"(gptr) : "memory");
}
#define CP_COMMIT() asm volatile("cp.async.commit_group;" ::: "memory")
#define CP_WAIT0()  asm volatile("cp.async.wait_group 0;" ::: "memory")

__device__ __forceinline__ void ldsm_x4(uint32_t* r, uint32_t addr) {
    asm volatile("ldmatrix.sync.aligned.m8n8.x4.shared.b16 {%0,%1,%2,%3}, [%4];"
                 : "=r"(r[0]), "=r"(r[1]), "=r"(r[2]), "=r"(r[3]) : "r"(addr));
}
__device__ __forceinline__ void ldsm_x2(uint32_t* r, uint32_t addr) {
    asm volatile("ldmatrix.sync.aligned.m8n8.x2.shared.b16 {%0,%1}, [%2];"
                 : "=r"(r[0]), "=r"(r[1]) : "r"(addr));
}

// mma.sync m16n8k16 bf16 -> fp32 (HMMA path; plain compute_80+ PTX)
__device__ __forceinline__ void mma16816(float* c, const uint32_t* a, const uint32_t* b) {
    asm volatile(
        "mma.sync.aligned.m16n8k16.row.col.f32.bf16.bf16.f32 "
        "{%0,%1,%2,%3}, {%4,%5,%6,%7}, {%8,%9}, {%0,%1,%2,%3};"
        : "+f"(c[0]), "+f"(c[1]), "+f"(c[2]), "+f"(c[3])
        : "r"(a[0]), "r"(a[1]), "r"(a[2]), "r"(a[3]), "r"(b[0]), "r"(b[1]));
}

__device__ __forceinline__ void split_hl(float v, __nv_bfloat16& h, __nv_bfloat16& l) {
    h = __float2bfloat16(v);
    l = __float2bfloat16(v - __bfloat162float(h));
}

// ---------------- zero scratch outputs (split-K accumulates via RED) -------
__global__ void __launch_bounds__(256) zero_kernel(float* __restrict__ out) {
    size_t i = ((size_t)blockIdx.x * 256 + threadIdx.x) * 4;
    float4 z = make_float4(0.f, 0.f, 0.f, 0.f);
    *(float4*)(g_q + i) = z;
    *(float4*)(g_k + i) = z;
    *(float4*)(g_v + i) = z;
    *(float4*)(out + i) = z;
}

// ---------------- operand conversion kernels -------------------------------
__global__ void __launch_bounds__(256) convert_x_kernel(const float* __restrict__ x) {
    size_t i = ((size_t)blockIdx.x * 256 + threadIdx.x) * 4;
    float4 v = *(const float4*)(x + i);
    float f[4] = {v.x, v.y, v.z, v.w};
    __nv_bfloat16 h[4], l[4];
#pragma unroll
    for (int j = 0; j < 4; j++) split_hl(f[j], h[j], l[j]);
    __nv_bfloat162 h01, h23, l01, l23;
    h01.x = h[0]; h01.y = h[1]; h23.x = h[2]; h23.y = h[3];
    l01.x = l[0]; l01.y = l[1]; l23.x = l[2]; l23.y = l[3];
    *(__nv_bfloat162*)(g_xh + i)     = h01;
    *(__nv_bfloat162*)(g_xh + i + 2) = h23;
    *(__nv_bfloat162*)(g_xl + i)     = l01;
    *(__nv_bfloat162*)(g_xl + i + 2) = l23;
}

// transpose W[K][N] -> Wt[N][K], split hi/lo
__global__ void __launch_bounds__(256) convert_w_kernel(
    const float* __restrict__ Wq, const float* __restrict__ Wk,
    const float* __restrict__ Wv, const float* __restrict__ Wo) {
    __shared__ float t[32][33];
    const float* W = (blockIdx.z == 0) ? Wq : (blockIdx.z == 1) ? Wk
                   : (blockIdx.z == 2) ? Wv : Wo;
    int n0 = blockIdx.x * 32, k0 = blockIdx.y * 32;
    int tx = threadIdx.x, ty = threadIdx.y;  // block (32,8)
#pragma unroll
    for (int r = 0; r < 4; r++)
        t[ty + 8 * r][tx] = W[(size_t)(k0 + ty + 8 * r) * Dn + n0 + tx];
    __syncthreads();
    size_t ob = (size_t)blockIdx.z * Dn * Dn;
#pragma unroll
    for (int r = 0; r < 4; r++) {
        float v = t[tx][ty + 8 * r];
        size_t o = ob + (size_t)(n0 + ty + 8 * r) * Dn + k0 + tx;
        __nv_bfloat16 h, l;
        split_hl(v, h, l);
        g_wth[o] = h;
        g_wtl[o] = l;
    }
}

// ---------------- bf16 3-term MMA GEMM (split-K): C += A @ Wt^T ------------
// 128x128 CTA tile, BK=32, 8 warps 2(M)x4(N), warp tile 64x32, ldmatrix frags.
// Each launch covers 16 k-chunks [kc0, kc0+16); output via fp32 RED (atomicAdd).
// (R8/R12-proven inner loop; do not templatize — reg pressure regression.)
#define KPAD 40                        // bf16 elems per smem row (32 + 8 pad)
#define TILE_E (128 * KPAD)            // elems per operand tile
#define STAGE_E (4 * TILE_E)           // Ah, Al, Bh, Bl
#define MM_SMEM_B (2 * STAGE_E * 2)    // 81920 bytes

__device__ __forceinline__ void mm_issue_stage(
    uint32_t sbase, int s, int kc, int tid,
    const __nv_bfloat16* Ah, const __nv_bfloat16* Al,
    const __nv_bfloat16* Bh, const __nv_bfloat16* Bl) {
    uint32_t st = sbase + (uint32_t)s * (STAGE_E * 2);
#pragma unroll
    for (int j = 0; j < 2; j++) {
        int idx = tid + j * 256;               // 0..511
        int row = idx >> 2, seg = idx & 3;
        size_t go = (size_t)row * Dn + kc * 32 + seg * 8;
        uint32_t so = (uint32_t)(row * KPAD + seg * 8) * 2;
        cp_async16(st + so,                    Ah + go);
        cp_async16(st + TILE_E * 2 + so,       Al + go);
        cp_async16(st + 2 * TILE_E * 2 + so,   Bh + go);
        cp_async16(st + 3 * TILE_E * 2 + so,   Bl + go);
    }
    CP_COMMIT();
}

__device__ __forceinline__ void mm_gemm_body(
    const __nv_bfloat16* __restrict__ Agh, const __nv_bfloat16* __restrict__ Agl,
    const __nv_bfloat16* __restrict__ Bgh, const __nv_bfloat16* __restrict__ Bgl,
    float* __restrict__ C, int kc0) {
    extern __shared__ __nv_bfloat16 sm[];
    const uint32_t sbase = smem_u32(sm);
    const int tid = threadIdx.x, lane = tid & 31, wid = tid >> 5;
    const int wm = wid & 1, wn = wid >> 1;
    const int m0 = blockIdx.y * 128, n0 = blockIdx.x * 128;

    const __nv_bfloat16* Ah = Agh + (size_t)m0 * Dn;
    const __nv_bfloat16* Al = Agl + (size_t)m0 * Dn;
    const __nv_bfloat16* Bh = Bgh + (size_t)n0 * Dn;
    const __nv_bfloat16* Bl = Bgl + (size_t)n0 * Dn;

    float c[4][4][4];
#pragma unroll
    for (int i = 0; i < 4; i++)
#pragma unroll
        for (int j = 0; j < 4; j++)
#pragma unroll
            for (int r = 0; r < 4; r++) c[i][j][r] = 0.f;

    mm_issue_stage(sbase, 0, kc0, tid, Ah, Al, Bh, Bl);

    // ldmatrix lane addressing (bf16 elements)
    const int a_r = (lane & 7) + ((lane >> 3) & 1) * 8;  // row in 16-row tile
    const int a_c = (lane >> 4) * 8;                     // k col-half 0/8
    const int b_r = lane & 7;                            // row in 8-row tile
    const int b_c = ((lane >> 3) & 1) * 8;               // k col-half (lanes 0-15)
    // epilogue addressing
    const int g4 = lane >> 2;
    const int cpair = (lane & 3) * 2;

    for (int i = 0; i < 16; i++) {
        CP_WAIT0();
        __syncthreads();
        if (i + 1 < 16)
            mm_issue_stage(sbase, (i + 1) & 1, kc0 + i + 1, tid, Ah, Al, Bh, Bl);

        const uint32_t st = sbase + (uint32_t)(i & 1) * (STAGE_E * 2);
        const uint32_t stAh = st;
        const uint32_t stAl = st + TILE_E * 2;
        const uint32_t stBh = st + 2 * TILE_E * 2;
        const uint32_t stBl = st + 3 * TILE_E * 2;

#pragma unroll
        for (int ks = 0; ks < 2; ks++) {
            const int kk = ks * 16;
            uint32_t bh[4][2], bl[4][2];
#pragma unroll
            for (int nf = 0; nf < 4; nf++) {
                uint32_t bo = (uint32_t)((wn * 32 + nf * 8 + b_r) * KPAD + kk + b_c) * 2;
                ldsm_x2(bh[nf], stBh + bo);
                ldsm_x2(bl[nf], stBl + bo);
            }
#pragma unroll
            for (int mf = 0; mf < 4; mf++) {
                uint32_t ao = (uint32_t)((wm * 64 + mf * 16 + a_r) * KPAD + kk + a_c) * 2;
                uint32_t ah[4], al[4];
                ldsm_x4(ah, stAh + ao);
                ldsm_x4(al, stAl + ao);
#pragma unroll
                for (int nf = 0; nf < 4; nf++) {
                    mma16816(c[mf][nf], ah, bh[nf]);
                    mma16816(c[mf][nf], ah, bl[nf]);
                    mma16816(c[mf][nf], al, bh[nf]);
                }
            }
        }
        __syncthreads();
    }

    // epilogue: accumulate fp32 C via RED (split-K partner adds the other half)
#pragma unroll
    for (int mf = 0; mf < 4; mf++) {
        int r = m0 + wm * 64 + mf * 16 + g4;
#pragma unroll
        for (int nf = 0; nf < 4; nf++) {
            int cc = n0 + wn * 32 + nf * 8 + cpair;
            float* p0 = C + (size_t)r * Dn + cc;
            float* p1 = C + (size_t)(r + 8) * Dn + cc;
            atomicAdd(p0,     c[mf][nf][0]);
            atomicAdd(p0 + 1, c[mf][nf][1]);
            atomicAdd(p1,     c[mf][nf][2]);
            atomicAdd(p1 + 1, c[mf][nf][3]);
        }
    }
}

__global__ void __launch_bounds__(256, 2) mm_qkv_kernel() {
    const int mat = blockIdx.z >> 1;
    const int kc0 = (blockIdx.z & 1) * 16;
    const size_t wo = (size_t)mat * Dn * Dn;
    float* C = (mat == 0) ? g_q : (mat == 1) ? g_k : g_v;
    mm_gemm_body(g_xh, g_xl, g_wth + wo, g_wtl + wo, C, kc0);
}
__global__ void __launch_bounds__(256, 2) mm_out_kernel(float* __restrict__ out) {
    mm_gemm_body(g_ah, g_al, g_wth + 3ull * Dn * Dn, g_wtl + 3ull * Dn * Dn,
                 out, (int)blockIdx.z * 16);
}

// ---------------- beta = sigmoid(x @ Wb + bb) ------------------------------
// 4 tokens/block, K split 4-ways, 512 blocks (fills the chip).
__global__ void __launch_bounds__(256) beta_kernel(const float* __restrict__ x,
                                                   const float* __restrict__ Wb,
                                                   const float* __restrict__ bbias) {
    __shared__ float sred[8][16];
    const int tid = threadIdx.x;
    const int h = tid & 15, q = (tid >> 4) & 3, t = tid >> 6;
    const int tok = blockIdx.x * 4 + t;
    const float* xr = x + (size_t)tok * Dn + q * 256;
    const float* wr = Wb + (size_t)(q * 256) * Hn + h;
    float a0 = 0.f, a1 = 0.f, a2 = 0.f, a3 = 0.f;
#pragma unroll 4
    for (int k = 0; k < 256; k += 4) {
        a0 += xr[k + 0] * wr[(size_t)(k + 0) * Hn];
        a1 += xr[k + 1] * wr[(size_t)(k + 1) * Hn];
        a2 += xr[k + 2] * wr[(size_t)(k + 2) * Hn];
        a3 += xr[k + 3] * wr[(size_t)(k + 3) * Hn];
    }
    float s = (a0 + a1) + (a2 + a3);
    s += __shfl_xor_sync(0xffffffffu, s, 16);
    const int wd = tid >> 5;
    if ((tid & 31) < 16) sred[wd][h] = s;
    __syncthreads();
    if (tid < 64) {
        int tt = tid >> 4, hh = tid & 15;
        float tot = sred[2 * tt][hh] + sred[2 * tt + 1][hh] + bbias[hh];
        g_beta[(size_t)(blockIdx.x * 4 + tt) * Hn + hh] = 1.f / (1.f + expf(-tot));
    }
}

// ---------------- per-chunk state delta: dS = (beta * k/||k||)^T @ v -------
// (l2norm fused: row norms computed during load via 16-lane shuffle)
__global__ void __launch_bounds__(256) chunk_delta_kernel() {
    __shared__ float skb[64 * 64];
    __shared__ float sv[64 * 64];
    __shared__ float sbeta[64];
    __shared__ float snorm[64];
    const int c = blockIdx.x, bh = blockIdx.y;
    const int b = bh >> 4, h = bh & 15;
    const int tid = threadIdx.x;
    const int tx = tid & 15, ty = tid >> 4;
    const size_t rowbase = (size_t)b * Ln + c * 64;

#pragma unroll
    for (int r = 0; r < 4; r++) {
        int t = r * 16 + (tid >> 4);
        int e4 = (tid & 15) * 4;
        size_t g = (rowbase + t) * Dn + h * 64 + e4;
        float4 kv = *(const float4*)&g_k[g];
        *(float4*)&skb[t * 64 + e4] = kv;
        *(float4*)&sv[t * 64 + e4] = *(const float4*)&g_v[g];
        float ss = kv.x * kv.x + kv.y * kv.y + kv.z * kv.z + kv.w * kv.w;
        ss += __shfl_xor_sync(0xffffffffu, ss, 1);
        ss += __shfl_xor_sync(0xffffffffu, ss, 2);
        ss += __shfl_xor_sync(0xffffffffu, ss, 4);
        ss += __shfl_xor_sync(0xffffffffu, ss, 8);
        if ((tid & 15) == 0) snorm[t] = ss;
    }
    __syncthreads();
    if (tid < 64)
        sbeta[tid] = g_beta[(rowbase + tid) * Hn + h] /
                     fmaxf(sqrtf(snorm[tid]), 1e-12f);
    __syncthreads();

    float acc[4][4];
#pragma unroll
    for (int i = 0; i < 4; i++)
#pragma unroll
        for (int j = 0; j < 4; j++) acc[i][j] = 0.f;
#pragma unroll 8
    for (int t = 0; t < 64; t++) {
        float4 a = *(const float4*)&skb[t * 64 + ty * 4];
        float s = sbeta[t];
        float4 b4 = *(const float4*)&sv[t * 64 + tx * 4];
        const float af[4] = {a.x * s, a.y * s, a.z * s, a.w * s};
        const float bf[4] = {b4.x, b4.y, b4.z, b4.w};
#pragma unroll
        for (int i = 0; i < 4; i++)
#pragma unroll
            for (int j = 0; j < 4; j++) acc[i][j] += af[i] * bf[j];
    }
    const size_t sbase = ((size_t)bh * NCn + c) * 4096;
#pragma unroll
    for (int i = 0; i < 4; i++)
        *(float4*)&g_sdelta[sbase + (ty * 4 + i) * 64 + tx * 4] =
            make_float4(acc[i][0], acc[i][1], acc[i][2], acc[i][3]);
}

// ---------------- exclusive prefix over 16 chunk states per (b,h) ----------
__global__ void __launch_bounds__(256) prefix_kernel() {
    const int bh = blockIdx.x;
    const int off = blockIdx.y * 1024 + threadIdx.x * 4;
    float4 acc = make_float4(0.f, 0.f, 0.f, 0.f);
    for (int c = 0; c < NCn; c++) {
        size_t base = ((size_t)bh * NCn + c) * 4096 + off;
        *(float4*)&g_sprefix[base] = acc;
        float4 d = *(const float4*)&g_sdelta[base];
        acc.x += d.x; acc.y += d.y; acc.z += d.z; acc.w += d.w;
    }
}

// ---------------- per-chunk output ----------------------------------------
// out = qn @ S_prev + tril(qn kn^T) * beta @ v ; q,k norms fused in.
__global__ void __launch_bounds__(256) chunk_out_kernel() {
    extern __shared__ float smf[];
    float* sqT = smf;             // [64][65] transposed raw q
    float* sX  = smf + 4160;      // multi-use
    float* sA  = smf + 8320;      // [64][64] A^T
    float* sbeta = smf + 12416;   // [64]
    float* sqn = smf + 12480;     // [64] ||q||^2
    float* skn = smf + 12544;     // [64] ||k||^2
    const int c = blockIdx.x, bh = blockIdx.y;
    const int b = bh >> 4, h = bh & 15;
    const int tid = threadIdx.x;
    const int tx = tid & 15, ty = tid >> 4;
    const size_t rowbase = (size_t)b * Ln + c * 64;
    const size_t sbase = ((size_t)bh * NCn + c) * 4096;

    if (tid < 64) sbeta[tid] = g_beta[(rowbase + tid) * Hn + h];
    // load q transposed + row sumsq
#pragma unroll
    for (int r = 0; r < 4; r++) {
        int t = r * 16 + (tid >> 4);
        int d4 = (tid & 15) * 4;
        float4 qv = *(const float4*)&g_q[(rowbase + t) * Dn + h * 64 + d4];
        sqT[(d4 + 0) * 65 + t] = qv.x;
        sqT[(d4 + 1) * 65 + t] = qv.y;
        sqT[(d4 + 2) * 65 + t] = qv.z;
        sqT[(d4 + 3) * 65 + t] = qv.w;
        float ss = qv.x * qv.x + qv.y * qv.y + qv.z * qv.z + qv.w * qv.w;
        ss += __shfl_xor_sync(0xffffffffu, ss, 1);
        ss += __shfl_xor_sync(0xffffffffu, ss, 2);
        ss += __shfl_xor_sync(0xffffffffu, ss, 4);
        ss += __shfl_xor_sync(0xffffffffu, ss, 8);
        if ((tid & 15) == 0) sqn[t] = ss;
    }
#pragma unroll
    for (int r = 0; r < 4; r++) {
        int idx = r * 1024 + tid * 4;
        *(float4*)&sX[idx] = *(const float4*)&g_sprefix[sbase + idx];
    }
    __syncthreads();

    float acc[4][4];
#pragma unroll
    for (int i = 0; i < 4; i++)
#pragma unroll
        for (int j = 0; j < 4; j++) acc[i][j] = 0.f;

    // phase 1: acc = q_raw @ S_prev  (1/||q|| applied at final write)
#pragma unroll 8
    for (int d = 0; d < 64; d++) {
        float a0 = sqT[d * 65 + ty * 4 + 0];
        float a1 = sqT[d * 65 + ty * 4 + 1];
        float a2v = sqT[d * 65 + ty * 4 + 2];
        float a3 = sqT[d * 65 + ty * 4 + 3];
        float4 bv = *(const float4*)&sX[d * 64 + tx * 4];
        acc[0][0] += a0 * bv.x; acc[0][1] += a0 * bv.y; acc[0][2] += a0 * bv.z; acc[0][3] += a0 * bv.w;
        acc[1][0] += a1 * bv.x; acc[1][1] += a1 * bv.y; acc[1][2] += a1 * bv.z; acc[1][3] += a1 * bv.w;
        acc[2][0] += a2v * bv.x; acc[2][1] += a2v * bv.y; acc[2][2] += a2v * bv.z; acc[2][3] += a2v * bv.w;
        acc[3][0] += a3 * bv.x; acc[3][1] += a3 * bv.y; acc[3][2] += a3 * bv.z; acc[3][3] += a3 * bv.w;
    }
    __syncthreads();
    // load k transposed into sX + row sumsq
#pragma unroll
    for (int r = 0; r < 4; r++) {
        int t = r * 16 + (tid >> 4);
        int d4 = (tid & 15) * 4;
        float4 kv = *(const float4*)&g_k[(rowbase + t) * Dn + h * 64 + d4];
        sX[(d4 + 0) * 65 + t] = kv.x;
        sX[(d4 + 1) * 65 + t] = kv.y;
        sX[(d4 + 2) * 65 + t] = kv.z;
        sX[(d4 + 3) * 65 + t] = kv.w;
        float ss = kv.x * kv.x + kv.y * kv.y + kv.z * kv.z + kv.w * kv.w;
        ss += __shfl_xor_sync(0xffffffffu, ss, 1);
        ss += __shfl_xor_sync(0xffffffffu, ss, 2);
        ss += __shfl_xor_sync(0xffffffffu, ss, 4);
        ss += __shfl_xor_sync(0xffffffffu, ss, 8);
        if ((tid & 15) == 0) skn[t] = ss;
    }
    __syncthreads();

    // phase 2: A[t][s] = q_t.k_s (raw); mask s<=t; scale beta[s]/||k_s||; store A^T
    float a2[4][4];
#pragma unroll
    for (int i = 0; i < 4; i++)
#pragma unroll
        for (int j = 0; j < 4; j++) a2[i][j] = 0.f;
#pragma unroll 8
    for (int d = 0; d < 64; d++) {
        float af[4], bf[4];
#pragma unroll
        for (int i = 0; i < 4; i++) af[i] = sqT[d * 65 + ty * 4 + i];
#pragma unroll
        for (int j = 0; j < 4; j++) bf[j] = sX[d * 65 + tx * 4 + j];
#pragma unroll
        for (int i = 0; i < 4; i++)
#pragma unroll
            for (int j = 0; j < 4; j++) a2[i][j] += af[i] * bf[j];
    }
#pragma unroll
    for (int j = 0; j < 4; j++) {
        int s = tx * 4 + j;
        float bscale = sbeta[s] / fmaxf(sqrtf(skn[s]), 1e-12f);
        float4 v4;
        v4.x = (s <= ty * 4 + 0) ? a2[0][j] * bscale : 0.f;
        v4.y = (s <= ty * 4 + 1) ? a2[1][j] * bscale : 0.f;
        v4.z = (s <= ty * 4 + 2) ? a2[2][j] * bscale : 0.f;
        v4.w = (s <= ty * 4 + 3) ? a2[3][j] * bscale : 0.f;
        *(float4*)&sA[s * 64 + ty * 4] = v4;
    }
    __syncthreads();
#pragma unroll
    for (int r = 0; r < 4; r++) {
        int t = r * 16 + (tid >> 4);
        int e4 = (tid & 15) * 4;
        *(float4*)&sX[t * 64 + e4] =
            *(const float4*)&g_v[(rowbase + t) * Dn + h * 64 + e4];
    }
    __syncthreads();

    // phase 3: acc += A @ v
#pragma unroll 8
    for (int s = 0; s < 64; s++) {
        float4 av = *(const float4*)&sA[s * 64 + ty * 4];
        float4 bv = *(const float4*)&sX[s * 64 + tx * 4];
        const float af[4] = {av.x, av.y, av.z, av.w};
        const float bf[4] = {bv.x, bv.y, bv.z, bv.w};
#pragma unroll
        for (int i = 0; i < 4; i++)
#pragma unroll
            for (int j = 0; j < 4; j++) acc[i][j] += af[i] * bf[j];
    }
    // write attn (scaled by 1/||q_t||) as bf16 hi/lo
#pragma unroll
    for (int i = 0; i < 4; i++) {
        int t = ty * 4 + i;
        float inq = 1.f / fmaxf(sqrtf(sqn[t]), 1e-12f);
        size_t base = (rowbase + t) * Dn + h * 64 + tx * 4;
        __nv_bfloat16 hh[4], ll[4];
#pragma unroll
        for (int j = 0; j < 4; j++) split_hl(acc[i][j] * inq, hh[j], ll[j]);
        __nv_bfloat162 h01, h23, l01, l23;
        h01.x = hh[0]; h01.y = hh[1]; h23.x = hh[2]; h23.y = hh[3];
        l01.x = ll[0]; l01.y = ll[1]; l23.x = ll[2]; l23.y = ll[3];
        *(__nv_bfloat162*)(g_ah + base)     = h01;
        *(__nv_bfloat162*)(g_ah + base + 2) = h23;
        *(__nv_bfloat162*)(g_al + base)     = l01;
        *(__nv_bfloat162*)(g_al + base + 2) = l23;
    }
}

// ---------------------------------------------------------------------------
extern "C" void kernel_launch(void* const* d_in, const int* in_sizes, int n_in,
                              void* d_out, int out_size) {
    const float* x  = (const float*)d_in[0];
    const float* Wq = (const float*)d_in[1];
    const float* Wk = (const float*)d_in[2];
    const float* Wv = (const float*)d_in[3];
    const float* Wo = (const float*)d_in[4];
    const float* Wb = (const float*)d_in[5];
    const float* bb = (const float*)d_in[6];
    float* out = (float*)d_out;

    cudaFuncSetAttribute(mm_qkv_kernel,
                         cudaFuncAttributeMaxDynamicSharedMemorySize, MM_SMEM_B);
    cudaFuncSetAttribute(mm_out_kernel,
                         cudaFuncAttributeMaxDynamicSharedMemorySize, MM_SMEM_B);
    cudaFuncSetAttribute(chunk_out_kernel,
                         cudaFuncAttributeMaxDynamicSharedMemorySize, 12608 * 4);

    // zero split-K accumulation targets (g_q/g_k/g_v and d_out)
    zero_kernel<<<NT * Dn / 1024, 256>>>(out);
    // operand conversion: x -> bf16 hi/lo, W -> W^T bf16 hi/lo
    convert_x_kernel<<<NT * Dn / 1024, 256>>>(x);
    convert_w_kernel<<<dim3(32, 32, 4), dim3(32, 8)>>>(Wq, Wk, Wv, Wo);
    // gates
    beta_kernel<<<NT / 4, 256>>>(x, Wb, bb);
    // q,k,v projections: 3 mats x 2 K-splits = 768 CTAs (split-K via RED)
    mm_qkv_kernel<<<dim3(Dn / 128, NT / 128, 6), 256, MM_SMEM_B>>>();
    // chunk-local state deltas (k-norm fused)
    chunk_delta_kernel<<<dim3(NCn, BHn), 256>>>();
    // exclusive prefix over chunk states
    prefix_kernel<<<dim3(BHn, 4), 256>>>();
    // per-chunk outputs (q/k-norm fused; writes attn bf16 hi/lo)
    chunk_out_kernel<<<dim3(NCn, BHn), 256, 12608 * 4>>>();
    // final projection: 2 K-splits = 256 CTAs (one full wave)
    mm_out_kernel<<<dim3(Dn / 128, NT / 128, 2), 256, MM_SMEM_B>>>(out);
}

// round 16
// speedup vs baseline: 1.1242x; 1.0595x over previous
#include <cuda_runtime.h>
#include <cuda_bf16.h>
#include <math.h>
#include <stdint.h>

#define Bn 2
#define Ln 1024
#define Dn 1024
#define Hn 16
#define HDn 64
#define NT 2048       // Bn*Ln tokens
#define NCn 16        // chunks per sequence (Ln/64)
#define BHn 32        // Bn*Hn

// ---------------- scratch (static device globals; no allocation allowed) ---
__device__ float g_q[NT * Dn];
__device__ float g_k[NT * Dn];
__device__ float g_v[NT * Dn];
__device__ float g_beta[NT * Hn];
__device__ float g_sdelta[BHn * NCn * HDn * HDn];
__device__ float g_sprefix[BHn * NCn * HDn * HDn];
// bf16 hi/lo operands for tensor-core GEMMs
__device__ __nv_bfloat16 g_xh[NT * Dn], g_xl[NT * Dn];
__device__ __nv_bfloat16 g_wth[4 * Dn * Dn], g_wtl[4 * Dn * Dn];  // W^T [N][K], 4 mats
__device__ __nv_bfloat16 g_ah[NT * Dn], g_al[NT * Dn];            // attn hi/lo

// =================== helpers ===============================================
__device__ __forceinline__ uint32_t smem_u32(const void* p) {
    uint32_t a;
    asm("{ .reg .u64 t; cvta.to.shared.u64 t, %1; cvt.u32.u64 %0, t; }"
        : "=r"(a) : "l"(p));
    return a;
}
__device__ __forceinline__ void cp_async16(uint32_t saddr, const void* gptr) {
    asm volatile("cp.async.cg.shared.global [%0], [%1], 16;"
                 :: "r"(saddr), "l"(gptr) : "memory");
}
#define CP_COMMIT() asm volatile("cp.async.commit_group;" ::: "memory")
#define CP_WAIT0()  asm volatile("cp.async.wait_group 0;" ::: "memory")

__device__ __forceinline__ void ldsm_x4(uint32_t* r, uint32_t addr) {
    asm volatile("ldmatrix.sync.aligned.m8n8.x4.shared.b16 {%0,%1,%2,%3}, [%4];"
                 : "=r"(r[0]), "=r"(r[1]), "=r"(r[2]), "=r"(r[3]) : "r"(addr));
}
__device__ __forceinline__ void ldsm_x2(uint32_t* r, uint32_t addr) {
    asm volatile("ldmatrix.sync.aligned.m8n8.x2.shared.b16 {%0,%1}, [%2];"
                 : "=r"(r[0]), "=r"(r[1]) : "r"(addr));
}

// mma.sync m16n8k16 bf16 -> fp32 (HMMA path; plain compute_80+ PTX)
__device__ __forceinline__ void mma16816(float* c, const uint32_t* a, const uint32_t* b) {
    asm volatile(
        "mma.sync.aligned.m16n8k16.row.col.f32.bf16.bf16.f32 "
        "{%0,%1,%2,%3}, {%4,%5,%6,%7}, {%8,%9}, {%0,%1,%2,%3};"
        : "+f"(c[0]), "+f"(c[1]), "+f"(c[2]), "+f"(c[3])
        : "r"(a[0]), "r"(a[1]), "r"(a[2]), "r"(a[3]), "r"(b[0]), "r"(b[1]));
}

__device__ __forceinline__ void split_hl(float v, __nv_bfloat16& h, __nv_bfloat16& l) {
    h = __float2bfloat16(v);
    l = __float2bfloat16(v - __bfloat162float(h));
}

// ---------------- operand conversion kernels -------------------------------
__global__ void __launch_bounds__(256) convert_x_kernel(const float* __restrict__ x) {
    size_t i = ((size_t)blockIdx.x * 256 + threadIdx.x) * 4;
    float4 v = *(const float4*)(x + i);
    float f[4] = {v.x, v.y, v.z, v.w};
    __nv_bfloat16 h[4], l[4];
#pragma unroll
    for (int j = 0; j < 4; j++) split_hl(f[j], h[j], l[j]);
    __nv_bfloat162 h01, h23, l01, l23;
    h01.x = h[0]; h01.y = h[1]; h23.x = h[2]; h23.y = h[3];
    l01.x = l[0]; l01.y = l[1]; l23.x = l[2]; l23.y = l[3];
    *(__nv_bfloat162*)(g_xh + i)     = h01;
    *(__nv_bfloat162*)(g_xh + i + 2) = h23;
    *(__nv_bfloat162*)(g_xl + i)     = l01;
    *(__nv_bfloat162*)(g_xl + i + 2) = l23;
}

// transpose W[K][N] -> Wt[N][K], split hi/lo
__global__ void __launch_bounds__(256) convert_w_kernel(
    const float* __restrict__ Wq, const float* __restrict__ Wk,
    const float* __restrict__ Wv, const float* __restrict__ Wo) {
    __shared__ float t[32][33];
    const float* W = (blockIdx.z == 0) ? Wq : (blockIdx.z == 1) ? Wk
                   : (blockIdx.z == 2) ? Wv : Wo;
    int n0 = blockIdx.x * 32, k0 = blockIdx.y * 32;
    int tx = threadIdx.x, ty = threadIdx.y;  // block (32,8)
#pragma unroll
    for (int r = 0; r < 4; r++)
        t[ty + 8 * r][tx] = W[(size_t)(k0 + ty + 8 * r) * Dn + n0 + tx];
    __syncthreads();
    size_t ob = (size_t)blockIdx.z * Dn * Dn;
#pragma unroll
    for (int r = 0; r < 4; r++) {
        float v = t[tx][ty + 8 * r];
        size_t o = ob + (size_t)(n0 + ty + 8 * r) * Dn + k0 + tx;
        __nv_bfloat16 h, l;
        split_hl(v, h, l);
        g_wth[o] = h;
        g_wtl[o] = l;
    }
}

// ---------------- bf16 3-term MMA GEMM: C[2048x1024] = A @ Wt^T ------------
// 128x128 CTA tile, BK=32, 8 warps 2(M)x4(N), warp tile 64x32, ldmatrix frags.
// Single __syncthreads per k-chunk: the top-of-iteration barrier both
// publishes the fresh stage and proves all warps finished reading the stage
// the next issue overwrites. (R8 inner loop otherwise; no templates.)
#define KPAD 40                        // bf16 elems per smem row (32 + 8 pad)
#define TILE_E (128 * KPAD)            // elems per operand tile
#define STAGE_E (4 * TILE_E)           // Ah, Al, Bh, Bl
#define MM_SMEM_B (2 * STAGE_E * 2)    // 81920 bytes

__device__ __forceinline__ void mm_issue_stage(
    uint32_t sbase, int s, int kc, int tid,
    const __nv_bfloat16* Ah, const __nv_bfloat16* Al,
    const __nv_bfloat16* Bh, const __nv_bfloat16* Bl) {
    uint32_t st = sbase + (uint32_t)s * (STAGE_E * 2);
#pragma unroll
    for (int j = 0; j < 2; j++) {
        int idx = tid + j * 256;               // 0..511
        int row = idx >> 2, seg = idx & 3;
        size_t go = (size_t)row * Dn + kc * 32 + seg * 8;
        uint32_t so = (uint32_t)(row * KPAD + seg * 8) * 2;
        cp_async16(st + so,                    Ah + go);
        cp_async16(st + TILE_E * 2 + so,       Al + go);
        cp_async16(st + 2 * TILE_E * 2 + so,   Bh + go);
        cp_async16(st + 3 * TILE_E * 2 + so,   Bl + go);
    }
    CP_COMMIT();
}

__device__ __forceinline__ void mm_gemm_body(
    const __nv_bfloat16* __restrict__ Agh, const __nv_bfloat16* __restrict__ Agl,
    const __nv_bfloat16* __restrict__ Bgh, const __nv_bfloat16* __restrict__ Bgl,
    float* __restrict__ C) {
    extern __shared__ __nv_bfloat16 sm[];
    const uint32_t sbase = smem_u32(sm);
    const int tid = threadIdx.x, lane = tid & 31, wid = tid >> 5;
    const int wm = wid & 1, wn = wid >> 1;
    const int m0 = blockIdx.y * 128, n0 = blockIdx.x * 128;

    const __nv_bfloat16* Ah = Agh + (size_t)m0 * Dn;
    const __nv_bfloat16* Al = Agl + (size_t)m0 * Dn;
    const __nv_bfloat16* Bh = Bgh + (size_t)n0 * Dn;
    const __nv_bfloat16* Bl = Bgl + (size_t)n0 * Dn;

    float c[4][4][4];
#pragma unroll
    for (int i = 0; i < 4; i++)
#pragma unroll
        for (int j = 0; j < 4; j++)
#pragma unroll
            for (int r = 0; r < 4; r++) c[i][j][r] = 0.f;

    mm_issue_stage(sbase, 0, 0, tid, Ah, Al, Bh, Bl);

    // ldmatrix lane addressing (bf16 elements)
    const int a_r = (lane & 7) + ((lane >> 3) & 1) * 8;  // row in 16-row tile
    const int a_c = (lane >> 4) * 8;                     // k col-half 0/8
    const int b_r = lane & 7;                            // row in 8-row tile
    const int b_c = ((lane >> 3) & 1) * 8;               // k col-half (lanes 0-15)
    // epilogue addressing
    const int g4 = lane >> 2;
    const int cpair = (lane & 3) * 2;

    for (int kc = 0; kc < 32; kc++) {
        CP_WAIT0();
        __syncthreads();   // publishes stage kc; proves stage (kc+1)&1 drained
        if (kc + 1 < 32)
            mm_issue_stage(sbase, (kc + 1) & 1, kc + 1, tid, Ah, Al, Bh, Bl);

        const uint32_t st = sbase + (uint32_t)(kc & 1) * (STAGE_E * 2);
        const uint32_t stAh = st;
        const uint32_t stAl = st + TILE_E * 2;
        const uint32_t stBh = st + 2 * TILE_E * 2;
        const uint32_t stBl = st + 3 * TILE_E * 2;

#pragma unroll
        for (int ks = 0; ks < 2; ks++) {
            const int kk = ks * 16;
            uint32_t bh[4][2], bl[4][2];
#pragma unroll
            for (int nf = 0; nf < 4; nf++) {
                uint32_t bo = (uint32_t)((wn * 32 + nf * 8 + b_r) * KPAD + kk + b_c) * 2;
                ldsm_x2(bh[nf], stBh + bo);
                ldsm_x2(bl[nf], stBl + bo);
            }
#pragma unroll
            for (int mf = 0; mf < 4; mf++) {
                uint32_t ao = (uint32_t)((wm * 64 + mf * 16 + a_r) * KPAD + kk + a_c) * 2;
                uint32_t ah[4], al[4];
                ldsm_x4(ah, stAh + ao);
                ldsm_x4(al, stAl + ao);
#pragma unroll
                for (int nf = 0; nf < 4; nf++) {
                    mma16816(c[mf][nf], ah, bh[nf]);
                    mma16816(c[mf][nf], ah, bl[nf]);
                    mma16816(c[mf][nf], al, bh[nf]);
                }
            }
        }
        // no trailing barrier: next iteration's top barrier covers the hazard
    }

    // epilogue: write fp32 C
#pragma unroll
    for (int mf = 0; mf < 4; mf++) {
        int r = m0 + wm * 64 + mf * 16 + g4;
#pragma unroll
        for (int nf = 0; nf < 4; nf++) {
            int cc = n0 + wn * 32 + nf * 8 + cpair;
            *(float2*)(C + (size_t)r * Dn + cc)       = make_float2(c[mf][nf][0], c[mf][nf][1]);
            *(float2*)(C + (size_t)(r + 8) * Dn + cc) = make_float2(c[mf][nf][2], c[mf][nf][3]);
        }
    }
}

__global__ void __launch_bounds__(256, 2) mm_qkv_kernel() {
    const size_t wo = (size_t)blockIdx.z * Dn * Dn;
    float* C = (blockIdx.z == 0) ? g_q : (blockIdx.z == 1) ? g_k : g_v;
    mm_gemm_body(g_xh, g_xl, g_wth + wo, g_wtl + wo, C);
}
__global__ void __launch_bounds__(256, 2) mm_out_kernel(float* __restrict__ out) {
    mm_gemm_body(g_ah, g_al, g_wth + 3ull * Dn * Dn, g_wtl + 3ull * Dn * Dn, out);
}

// ---------------- beta = sigmoid(x @ Wb + bb) ------------------------------
// R8-measured version (16.4us): 16 tokens/block, smem tiles, 128 blocks.
__global__ void __launch_bounds__(256) beta_kernel(const float* __restrict__ x,
                                                   const float* __restrict__ Wb,
                                                   const float* __restrict__ bbias) {
    __shared__ float sx[16 * 64];
    __shared__ float sW[64 * 16];
    const int tid = threadIdx.x;
    const int tx = tid & 15, ty = tid >> 4;
    const int row0 = blockIdx.x * 16;
    float acc = 0.f;
    for (int k0 = 0; k0 < Dn; k0 += 64) {
        {
            int r = tid >> 4, c4 = (tid & 15) * 4;
            *(float4*)&sx[r * 64 + c4] =
                *(const float4*)&x[(size_t)(row0 + r) * Dn + k0 + c4];
            int wr = tid >> 2, wc4 = (tid & 3) * 4;
            *(float4*)&sW[wr * 16 + wc4] =
                *(const float4*)&Wb[(size_t)(k0 + wr) * Hn + wc4];
        }
        __syncthreads();
#pragma unroll
        for (int kk = 0; kk < 64; kk++)
            acc += sx[ty * 64 + kk] * sW[kk * 16 + tx];
        __syncthreads();
    }
    acc += bbias[tx];
    g_beta[(size_t)(row0 + ty) * Hn + tx] = 1.f / (1.f + expf(-acc));
}

// ---------------- per-chunk state delta: dS = (beta * k/||k||)^T @ v -------
// (l2norm fused: row norms computed during load via 16-lane shuffle)
__global__ void __launch_bounds__(256) chunk_delta_kernel() {
    __shared__ float skb[64 * 64];
    __shared__ float sv[64 * 64];
    __shared__ float sbeta[64];
    __shared__ float snorm[64];
    const int c = blockIdx.x, bh = blockIdx.y;
    const int b = bh >> 4, h = bh & 15;
    const int tid = threadIdx.x;
    const int tx = tid & 15, ty = tid >> 4;
    const size_t rowbase = (size_t)b * Ln + c * 64;

#pragma unroll
    for (int r = 0; r < 4; r++) {
        int t = r * 16 + (tid >> 4);
        int e4 = (tid & 15) * 4;
        size_t g = (rowbase + t) * Dn + h * 64 + e4;
        float4 kv = *(const float4*)&g_k[g];
        *(float4*)&skb[t * 64 + e4] = kv;
        *(float4*)&sv[t * 64 + e4] = *(const float4*)&g_v[g];
        float ss = kv.x * kv.x + kv.y * kv.y + kv.z * kv.z + kv.w * kv.w;
        ss += __shfl_xor_sync(0xffffffffu, ss, 1);
        ss += __shfl_xor_sync(0xffffffffu, ss, 2);
        ss += __shfl_xor_sync(0xffffffffu, ss, 4);
        ss += __shfl_xor_sync(0xffffffffu, ss, 8);
        if ((tid & 15) == 0) snorm[t] = ss;
    }
    __syncthreads();
    if (tid < 64)
        sbeta[tid] = g_beta[(rowbase + tid) * Hn + h] /
                     fmaxf(sqrtf(snorm[tid]), 1e-12f);
    __syncthreads();

    float acc[4][4];
#pragma unroll
    for (int i = 0; i < 4; i++)
#pragma unroll
        for (int j = 0; j < 4; j++) acc[i][j] = 0.f;
#pragma unroll 8
    for (int t = 0; t < 64; t++) {
        float4 a = *(const float4*)&skb[t * 64 + ty * 4];
        float s = sbeta[t];
        float4 b4 = *(const float4*)&sv[t * 64 + tx * 4];
        const float af[4] = {a.x * s, a.y * s, a.z * s, a.w * s};
        const float bf[4] = {b4.x, b4.y, b4.z, b4.w};
#pragma unroll
        for (int i = 0; i < 4; i++)
#pragma unroll
            for (int j = 0; j < 4; j++) acc[i][j] += af[i] * bf[j];
    }
    const size_t sbase = ((size_t)bh * NCn + c) * 4096;
#pragma unroll
    for (int i = 0; i < 4; i++)
        *(float4*)&g_sdelta[sbase + (ty * 4 + i) * 64 + tx * 4] =
            make_float4(acc[i][0], acc[i][1], acc[i][2], acc[i][3]);
}

// ---------------- exclusive prefix over 16 chunk states per (b,h) ----------
__global__ void __launch_bounds__(256) prefix_kernel() {
    const int bh = blockIdx.x;
    const int off = blockIdx.y * 1024 + threadIdx.x * 4;
    float4 acc = make_float4(0.f, 0.f, 0.f, 0.f);
    for (int c = 0; c < NCn; c++) {
        size_t base = ((size_t)bh * NCn + c) * 4096 + off;
        *(float4*)&g_sprefix[base] = acc;
        float4 d = *(const float4*)&g_sdelta[base];
        acc.x += d.x; acc.y += d.y; acc.z += d.z; acc.w += d.w;
    }
}

// ---------------- per-chunk output ----------------------------------------
// out = qn @ S_prev + tril(qn kn^T) * beta @ v ; q,k norms fused in.
__global__ void __launch_bounds__(256) chunk_out_kernel() {
    extern __shared__ float smf[];
    float* sqT = smf;             // [64][65] transposed raw q
    float* sX  = smf + 4160;      // multi-use
    float* sA  = smf + 8320;      // [64][64] A^T
    float* sbeta = smf + 12416;   // [64]
    float* sqn = smf + 12480;     // [64] ||q||^2
    float* skn = smf + 12544;     // [64] ||k||^2
    const int c = blockIdx.x, bh = blockIdx.y;
    const int b = bh >> 4, h = bh & 15;
    const int tid = threadIdx.x;
    const int tx = tid & 15, ty = tid >> 4;
    const size_t rowbase = (size_t)b * Ln + c * 64;
    const size_t sbase = ((size_t)bh * NCn + c) * 4096;

    if (tid < 64) sbeta[tid] = g_beta[(rowbase + tid) * Hn + h];
    // load q transposed + row sumsq
#pragma unroll
    for (int r = 0; r < 4; r++) {
        int t = r * 16 + (tid >> 4);
        int d4 = (tid & 15) * 4;
        float4 qv = *(const float4*)&g_q[(rowbase + t) * Dn + h * 64 + d4];
        sqT[(d4 + 0) * 65 + t] = qv.x;
        sqT[(d4 + 1) * 65 + t] = qv.y;
        sqT[(d4 + 2) * 65 + t] = qv.z;
        sqT[(d4 + 3) * 65 + t] = qv.w;
        float ss = qv.x * qv.x + qv.y * qv.y + qv.z * qv.z + qv.w * qv.w;
        ss += __shfl_xor_sync(0xffffffffu, ss, 1);
        ss += __shfl_xor_sync(0xffffffffu, ss, 2);
        ss += __shfl_xor_sync(0xffffffffu, ss, 4);
        ss += __shfl_xor_sync(0xffffffffu, ss, 8);
        if ((tid & 15) == 0) sqn[t] = ss;
    }
#pragma unroll
    for (int r = 0; r < 4; r++) {
        int idx = r * 1024 + tid * 4;
        *(float4*)&sX[idx] = *(const float4*)&g_sprefix[sbase + idx];
    }
    __syncthreads();

    float acc[4][4];
#pragma unroll
    for (int i = 0; i < 4; i++)
#pragma unroll
        for (int j = 0; j < 4; j++) acc[i][j] = 0.f;

    // phase 1: acc = q_raw @ S_prev  (1/||q|| applied at final write)
#pragma unroll 8
    for (int d = 0; d < 64; d++) {
        float a0 = sqT[d * 65 + ty * 4 + 0];
        float a1 = sqT[d * 65 + ty * 4 + 1];
        float a2v = sqT[d * 65 + ty * 4 + 2];
        float a3 = sqT[d * 65 + ty * 4 + 3];
        float4 bv = *(const float4*)&sX[d * 64 + tx * 4];
        acc[0][0] += a0 * bv.x; acc[0][1] += a0 * bv.y; acc[0][2] += a0 * bv.z; acc[0][3] += a0 * bv.w;
        acc[1][0] += a1 * bv.x; acc[1][1] += a1 * bv.y; acc[1][2] += a1 * bv.z; acc[1][3] += a1 * bv.w;
        acc[2][0] += a2v * bv.x; acc[2][1] += a2v * bv.y; acc[2][2] += a2v * bv.z; acc[2][3] += a2v * bv.w;
        acc[3][0] += a3 * bv.x; acc[3][1] += a3 * bv.y; acc[3][2] += a3 * bv.z; acc[3][3] += a3 * bv.w;
    }
    __syncthreads();
    // load k transposed into sX + row sumsq
#pragma unroll
    for (int r = 0; r < 4; r++) {
        int t = r * 16 + (tid >> 4);
        int d4 = (tid & 15) * 4;
        float4 kv = *(const float4*)&g_k[(rowbase + t) * Dn + h * 64 + d4];
        sX[(d4 + 0) * 65 + t] = kv.x;
        sX[(d4 + 1) * 65 + t] = kv.y;
        sX[(d4 + 2) * 65 + t] = kv.z;
        sX[(d4 + 3) * 65 + t] = kv.w;
        float ss = kv.x * kv.x + kv.y * kv.y + kv.z * kv.z + kv.w * kv.w;
        ss += __shfl_xor_sync(0xffffffffu, ss, 1);
        ss += __shfl_xor_sync(0xffffffffu, ss, 2);
        ss += __shfl_xor_sync(0xffffffffu, ss, 4);
        ss += __shfl_xor_sync(0xffffffffu, ss, 8);
        if ((tid & 15) == 0) skn[t] = ss;
    }
    __syncthreads();

    // phase 2: A[t][s] = q_t.k_s (raw); mask s<=t; scale beta[s]/||k_s||; store A^T
    float a2[4][4];
#pragma unroll
    for (int i = 0; i < 4; i++)
#pragma unroll
        for (int j = 0; j < 4; j++) a2[i][j] = 0.f;
#pragma unroll 8
    for (int d = 0; d < 64; d++) {
        float af[4], bf[4];
#pragma unroll
        for (int i = 0; i < 4; i++) af[i] = sqT[d * 65 + ty * 4 + i];
#pragma unroll
        for (int j = 0; j < 4; j++) bf[j] = sX[d * 65 + tx * 4 + j];
#pragma unroll
        for (int i = 0; i < 4; i++)
#pragma unroll
            for (int j = 0; j < 4; j++) a2[i][j] += af[i] * bf[j];
    }
#pragma unroll
    for (int j = 0; j < 4; j++) {
        int s = tx * 4 + j;
        float bscale = sbeta[s] / fmaxf(sqrtf(skn[s]), 1e-12f);
        float4 v4;
        v4.x = (s <= ty * 4 + 0) ? a2[0][j] * bscale : 0.f;
        v4.y = (s <= ty * 4 + 1) ? a2[1][j] * bscale : 0.f;
        v4.z = (s <= ty * 4 + 2) ? a2[2][j] * bscale : 0.f;
        v4.w = (s <= ty * 4 + 3) ? a2[3][j] * bscale : 0.f;
        *(float4*)&sA[s * 64 + ty * 4] = v4;
    }
    __syncthreads();
#pragma unroll
    for (int r = 0; r < 4; r++) {
        int t = r * 16 + (tid >> 4);
        int e4 = (tid & 15) * 4;
        *(float4*)&sX[t * 64 + e4] =
            *(const float4*)&g_v[(rowbase + t) * Dn + h * 64 + e4];
    }
    __syncthreads();

    // phase 3: acc += A @ v
#pragma unroll 8
    for (int s = 0; s < 64; s++) {
        float4 av = *(const float4*)&sA[s * 64 + ty * 4];
        float4 bv = *(const float4*)&sX[s * 64 + tx * 4];
        const float af[4] = {av.x, av.y, av.z, av.w};
        const float bf[4] = {bv.x, bv.y, bv.z, bv.w};
#pragma unroll
        for (int i = 0; i < 4; i++)
#pragma unroll
            for (int j = 0; j < 4; j++) acc[i][j] += af[i] * bf[j];
    }
    // write attn (scaled by 1/||q_t||) as bf16 hi/lo
#pragma unroll
    for (int i = 0; i < 4; i++) {
        int t = ty * 4 + i;
        float inq = 1.f / fmaxf(sqrtf(sqn[t]), 1e-12f);
        size_t base = (rowbase + t) * Dn + h * 64 + tx * 4;
        __nv_bfloat16 hh[4], ll[4];
#pragma unroll
        for (int j = 0; j < 4; j++) split_hl(acc[i][j] * inq, hh[j], ll[j]);
        __nv_bfloat162 h01, h23, l01, l23;
        h01.x = hh[0]; h01.y = hh[1]; h23.x = hh[2]; h23.y = hh[3];
        l01.x = ll[0]; l01.y = ll[1]; l23.x = ll[2]; l23.y = ll[3];
        *(__nv_bfloat162*)(g_ah + base)     = h01;
        *(__nv_bfloat162*)(g_ah + base + 2) = h23;
        *(__nv_bfloat162*)(g_al + base)     = l01;
        *(__nv_bfloat162*)(g_al + base + 2) = l23;
    }
}

// ---------------------------------------------------------------------------
extern "C" void kernel_launch(void* const* d_in, const int* in_sizes, int n_in,
                              void* d_out, int out_size) {
    const float* x  = (const float*)d_in[0];
    const float* Wq = (const float*)d_in[1];
    const float* Wk = (const float*)d_in[2];
    const float* Wv = (const float*)d_in[3];
    const float* Wo = (const float*)d_in[4];
    const float* Wb = (const float*)d_in[5];
    const float* bb = (const float*)d_in[6];
    float* out = (float*)d_out;

    cudaFuncSetAttribute(mm_qkv_kernel,
                         cudaFuncAttributeMaxDynamicSharedMemorySize, MM_SMEM_B);
    cudaFuncSetAttribute(mm_out_kernel,
                         cudaFuncAttributeMaxDynamicSharedMemorySize, MM_SMEM_B);
    cudaFuncSetAttribute(chunk_out_kernel,
                         cudaFuncAttributeMaxDynamicSharedMemorySize, 12608 * 4);

    // operand conversion: x -> bf16 hi/lo, W -> W^T bf16 hi/lo
    convert_x_kernel<<<NT * Dn / 1024, 256>>>(x);
    convert_w_kernel<<<dim3(32, 32, 4), dim3(32, 8)>>>(Wq, Wk, Wv, Wo);
    // gates (before mm_qkv so mm_qkv lands in the ncu capture slot)
    beta_kernel<<<NT / 16, 256>>>(x, Wb, bb);
    // q,k,v projections on tensor cores (3-term bf16 hi/lo)
    mm_qkv_kernel<<<dim3(Dn / 128, NT / 128, 3), 256, MM_SMEM_B>>>();
    // chunk-local state deltas (k-norm fused)
    chunk_delta_kernel<<<dim3(NCn, BHn), 256>>>();
    // exclusive prefix over chunk states
    prefix_kernel<<<dim3(BHn, 4), 256>>>();
    // per-chunk outputs (q/k-norm fused; writes attn bf16 hi/lo)
    chunk_out_kernel<<<dim3(NCn, BHn), 256, 12608 * 4>>>();
    // final projection on tensor cores
    mm_out_kernel<<<dim3(Dn / 128, NT / 128), 256, MM_SMEM_B>>>(out);
}

// round 17
// speedup vs baseline: 1.5793x; 1.4049x over previous
#include <cuda_runtime.h>
#include <cuda_bf16.h>
#include <cuda_fp16.h>
#include <math.h>
#include <stdint.h>

#define Bn 2
#define Ln 1024
#define Dn 1024
#define Hn 16
#define HDn 64
#define NT 2048       // Bn*Ln tokens
#define NCn 16        // chunks per sequence (Ln/64)
#define BHn 32        // Bn*Hn

// ---------------- scratch (static device globals; no allocation allowed) ---
__device__ float g_q[NT * Dn];
__device__ float g_k[NT * Dn];
__device__ float g_v[NT * Dn];
__device__ float g_beta[NT * Hn];
__device__ float g_sdelta[BHn * NCn * HDn * HDn];
__device__ float g_sprefix[BHn * NCn * HDn * HDn];
// fp16 operands for qkv projections (single-term; rel-err budget 1e-3)
__device__ __half g_xf[NT * Dn];
__device__ __half g_wtf[3 * Dn * Dn];            // W^T [N][K] fp16, q/k/v
// bf16 hi/lo operands for the (3-term) output GEMM
__device__ __nv_bfloat16 g_wth[Dn * Dn], g_wtl[Dn * Dn];  // Wo^T hi/lo
__device__ __nv_bfloat16 g_ah[NT * Dn], g_al[NT * Dn];    // attn hi/lo

// =================== helpers ===============================================
__device__ __forceinline__ uint32_t smem_u32(const void* p) {
    uint32_t a;
    asm("{ .reg .u64 t; cvta.to.shared.u64 t, %1; cvt.u32.u64 %0, t; }"
        : "=r"(a) : "l"(p));
    return a;
}
__device__ __forceinline__ void cp_async16(uint32_t saddr, const void* gptr) {
    asm volatile("cp.async.cg.shared.global [%0], [%1], 16;"
                 :: "r"(saddr), "l"(gptr) : "memory");
}
#define CP_COMMIT() asm volatile("cp.async.commit_group;" ::: "memory")
#define CP_WAIT0()  asm volatile("cp.async.wait_group 0;" ::: "memory")

__device__ __forceinline__ void ldsm_x4(uint32_t* r, uint32_t addr) {
    asm volatile("ldmatrix.sync.aligned.m8n8.x4.shared.b16 {%0,%1,%2,%3}, [%4];"
                 : "=r"(r[0]), "=r"(r[1]), "=r"(r[2]), "=r"(r[3]) : "r"(addr));
}
__device__ __forceinline__ void ldsm_x2(uint32_t* r, uint32_t addr) {
    asm volatile("ldmatrix.sync.aligned.m8n8.x2.shared.b16 {%0,%1}, [%2];"
                 : "=r"(r[0]), "=r"(r[1]) : "r"(addr));
}

// mma.sync m16n8k16 bf16 -> fp32
__device__ __forceinline__ void mma16816(float* c, const uint32_t* a, const uint32_t* b) {
    asm volatile(
        "mma.sync.aligned.m16n8k16.row.col.f32.bf16.bf16.f32 "
        "{%0,%1,%2,%3}, {%4,%5,%6,%7}, {%8,%9}, {%0,%1,%2,%3};"
        : "+f"(c[0]), "+f"(c[1]), "+f"(c[2]), "+f"(c[3])
        : "r"(a[0]), "r"(a[1]), "r"(a[2]), "r"(a[3]), "r"(b[0]), "r"(b[1]));
}
// mma.sync m16n8k16 fp16 -> fp32
__device__ __forceinline__ void mma16816h(float* c, const uint32_t* a, const uint32_t* b) {
    asm volatile(
        "mma.sync.aligned.m16n8k16.row.col.f32.f16.f16.f32 "
        "{%0,%1,%2,%3}, {%4,%5,%6,%7}, {%8,%9}, {%0,%1,%2,%3};"
        : "+f"(c[0]), "+f"(c[1]), "+f"(c[2]), "+f"(c[3])
        : "r"(a[0]), "r"(a[1]), "r"(a[2]), "r"(a[3]), "r"(b[0]), "r"(b[1]));
}

__device__ __forceinline__ void split_hl(float v, __nv_bfloat16& h, __nv_bfloat16& l) {
    h = __float2bfloat16(v);
    l = __float2bfloat16(v - __bfloat162float(h));
}

// ---------------- operand conversion kernels -------------------------------
__global__ void __launch_bounds__(256) convert_x_kernel(const float* __restrict__ x) {
    size_t i = ((size_t)blockIdx.x * 256 + threadIdx.x) * 4;
    float4 v = *(const float4*)(x + i);
    __half2 a, b;
    a.x = __float2half(v.x); a.y = __float2half(v.y);
    b.x = __float2half(v.z); b.y = __float2half(v.w);
    *(__half2*)(g_xf + i)     = a;
    *(__half2*)(g_xf + i + 2) = b;
}

// transpose W[K][N] -> Wt[N][K]; q/k/v -> fp16, Wo -> bf16 hi/lo
__global__ void __launch_bounds__(256) convert_w_kernel(
    const float* __restrict__ Wq, const float* __restrict__ Wk,
    const float* __restrict__ Wv, const float* __restrict__ Wo) {
    __shared__ float t[32][33];
    const float* W = (blockIdx.z == 0) ? Wq : (blockIdx.z == 1) ? Wk
                   : (blockIdx.z == 2) ? Wv : Wo;
    int n0 = blockIdx.x * 32, k0 = blockIdx.y * 32;
    int tx = threadIdx.x, ty = threadIdx.y;  // block (32,8)
#pragma unroll
    for (int r = 0; r < 4; r++)
        t[ty + 8 * r][tx] = W[(size_t)(k0 + ty + 8 * r) * Dn + n0 + tx];
    __syncthreads();
    if (blockIdx.z < 3) {
        size_t ob = (size_t)blockIdx.z * Dn * Dn;
#pragma unroll
        for (int r = 0; r < 4; r++) {
            float v = t[tx][ty + 8 * r];
            g_wtf[ob + (size_t)(n0 + ty + 8 * r) * Dn + k0 + tx] = __float2half(v);
        }
    } else {
#pragma unroll
        for (int r = 0; r < 4; r++) {
            float v = t[tx][ty + 8 * r];
            size_t o = (size_t)(n0 + ty + 8 * r) * Dn + k0 + tx;
            __nv_bfloat16 h, l;
            split_hl(v, h, l);
            g_wth[o] = h;
            g_wtl[o] = l;
        }
    }
}

#define KPAD 40                        // 16-bit elems per smem row (32 + 8 pad)
#define TILE_E (128 * KPAD)            // elems per operand tile

// ---------------- fp16 single-term MMA GEMM: C = A @ Wt^T ------------------
// 128x128 CTA tile, BK=32, 8 warps 2(M)x4(N), warp tile 64x32, ldmatrix frags.
#define STG16_E (2 * TILE_E)           // A, B
#define MM16_SMEM_B (2 * STG16_E * 2)  // 40960 bytes

__device__ __forceinline__ void mm16_issue_stage(
    uint32_t sbase, int s, int kc, int tid,
    const __half* A, const __half* B) {
    uint32_t st = sbase + (uint32_t)s * (STG16_E * 2);
#pragma unroll
    for (int j = 0; j < 2; j++) {
        int idx = tid + j * 256;               // 0..511
        int row = idx >> 2, seg = idx & 3;
        size_t go = (size_t)row * Dn + kc * 32 + seg * 8;
        uint32_t so = (uint32_t)(row * KPAD + seg * 8) * 2;
        cp_async16(st + so,              A + go);
        cp_async16(st + TILE_E * 2 + so, B + go);
    }
    CP_COMMIT();
}

__global__ void __launch_bounds__(256, 2) mm_qkv_kernel() {
    extern __shared__ __half smh[];
    const uint32_t sbase = smem_u32(smh);
    const int tid = threadIdx.x, lane = tid & 31, wid = tid >> 5;
    const int wm = wid & 1, wn = wid >> 1;
    const int m0 = blockIdx.y * 128, n0 = blockIdx.x * 128;
    const size_t wo = (size_t)blockIdx.z * Dn * Dn;
    float* C = (blockIdx.z == 0) ? g_q : (blockIdx.z == 1) ? g_k : g_v;

    const __half* A = g_xf + (size_t)m0 * Dn;
    const __half* B = g_wtf + wo + (size_t)n0 * Dn;

    float c[4][4][4];
#pragma unroll
    for (int i = 0; i < 4; i++)
#pragma unroll
        for (int j = 0; j < 4; j++)
#pragma unroll
            for (int r = 0; r < 4; r++) c[i][j][r] = 0.f;

    mm16_issue_stage(sbase, 0, 0, tid, A, B);

    const int a_r = (lane & 7) + ((lane >> 3) & 1) * 8;
    const int a_c = (lane >> 4) * 8;
    const int b_r = lane & 7;
    const int b_c = ((lane >> 3) & 1) * 8;
    const int g4 = lane >> 2;
    const int cpair = (lane & 3) * 2;

    for (int kc = 0; kc < 32; kc++) {
        CP_WAIT0();
        __syncthreads();
        if (kc + 1 < 32)
            mm16_issue_stage(sbase, (kc + 1) & 1, kc + 1, tid, A, B);

        const uint32_t st = sbase + (uint32_t)(kc & 1) * (STG16_E * 2);
        const uint32_t stA = st;
        const uint32_t stB = st + TILE_E * 2;

#pragma unroll
        for (int ks = 0; ks < 2; ks++) {
            const int kk = ks * 16;
            uint32_t bh[4][2];
#pragma unroll
            for (int nf = 0; nf < 4; nf++) {
                uint32_t bo = (uint32_t)((wn * 32 + nf * 8 + b_r) * KPAD + kk + b_c) * 2;
                ldsm_x2(bh[nf], stB + bo);
            }
#pragma unroll
            for (int mf = 0; mf < 4; mf++) {
                uint32_t ao = (uint32_t)((wm * 64 + mf * 16 + a_r) * KPAD + kk + a_c) * 2;
                uint32_t ah[4];
                ldsm_x4(ah, stA + ao);
#pragma unroll
                for (int nf = 0; nf < 4; nf++)
                    mma16816h(c[mf][nf], ah, bh[nf]);
            }
        }
    }

#pragma unroll
    for (int mf = 0; mf < 4; mf++) {
        int r = m0 + wm * 64 + mf * 16 + g4;
#pragma unroll
        for (int nf = 0; nf < 4; nf++) {
            int cc = n0 + wn * 32 + nf * 8 + cpair;
            *(float2*)(C + (size_t)r * Dn + cc)       = make_float2(c[mf][nf][0], c[mf][nf][1]);
            *(float2*)(C + (size_t)(r + 8) * Dn + cc) = make_float2(c[mf][nf][2], c[mf][nf][3]);
        }
    }
}

// ---------------- bf16 3-term MMA GEMM for the output projection -----------
// (R8/R16-proven path; single barrier per k-chunk.)
#define STAGE_E (4 * TILE_E)           // Ah, Al, Bh, Bl
#define MM_SMEM_B (2 * STAGE_E * 2)    // 81920 bytes

__device__ __forceinline__ void mm_issue_stage(
    uint32_t sbase, int s, int kc, int tid,
    const __nv_bfloat16* Ah, const __nv_bfloat16* Al,
    const __nv_bfloat16* Bh, const __nv_bfloat16* Bl) {
    uint32_t st = sbase + (uint32_t)s * (STAGE_E * 2);
#pragma unroll
    for (int j = 0; j < 2; j++) {
        int idx = tid + j * 256;               // 0..511
        int row = idx >> 2, seg = idx & 3;
        size_t go = (size_t)row * Dn + kc * 32 + seg * 8;
        uint32_t so = (uint32_t)(row * KPAD + seg * 8) * 2;
        cp_async16(st + so,                    Ah + go);
        cp_async16(st + TILE_E * 2 + so,       Al + go);
        cp_async16(st + 2 * TILE_E * 2 + so,   Bh + go);
        cp_async16(st + 3 * TILE_E * 2 + so,   Bl + go);
    }
    CP_COMMIT();
}

__global__ void __launch_bounds__(256, 2) mm_out_kernel(float* __restrict__ out) {
    extern __shared__ __nv_bfloat16 smb[];
    const uint32_t sbase = smem_u32(smb);
    const int tid = threadIdx.x, lane = tid & 31, wid = tid >> 5;
    const int wm = wid & 1, wn = wid >> 1;
    const int m0 = blockIdx.y * 128, n0 = blockIdx.x * 128;

    const __nv_bfloat16* Ah = g_ah + (size_t)m0 * Dn;
    const __nv_bfloat16* Al = g_al + (size_t)m0 * Dn;
    const __nv_bfloat16* Bh = g_wth + (size_t)n0 * Dn;
    const __nv_bfloat16* Bl = g_wtl + (size_t)n0 * Dn;

    float c[4][4][4];
#pragma unroll
    for (int i = 0; i < 4; i++)
#pragma unroll
        for (int j = 0; j < 4; j++)
#pragma unroll
            for (int r = 0; r < 4; r++) c[i][j][r] = 0.f;

    mm_issue_stage(sbase, 0, 0, tid, Ah, Al, Bh, Bl);

    const int a_r = (lane & 7) + ((lane >> 3) & 1) * 8;
    const int a_c = (lane >> 4) * 8;
    const int b_r = lane & 7;
    const int b_c = ((lane >> 3) & 1) * 8;
    const int g4 = lane >> 2;
    const int cpair = (lane & 3) * 2;

    for (int kc = 0; kc < 32; kc++) {
        CP_WAIT0();
        __syncthreads();
        if (kc + 1 < 32)
            mm_issue_stage(sbase, (kc + 1) & 1, kc + 1, tid, Ah, Al, Bh, Bl);

        const uint32_t st = sbase + (uint32_t)(kc & 1) * (STAGE_E * 2);
        const uint32_t stAh = st;
        const uint32_t stAl = st + TILE_E * 2;
        const uint32_t stBh = st + 2 * TILE_E * 2;
        const uint32_t stBl = st + 3 * TILE_E * 2;

#pragma unroll
        for (int ks = 0; ks < 2; ks++) {
            const int kk = ks * 16;
            uint32_t bh[4][2], bl[4][2];
#pragma unroll
            for (int nf = 0; nf < 4; nf++) {
                uint32_t bo = (uint32_t)((wn * 32 + nf * 8 + b_r) * KPAD + kk + b_c) * 2;
                ldsm_x2(bh[nf], stBh + bo);
                ldsm_x2(bl[nf], stBl + bo);
            }
#pragma unroll
            for (int mf = 0; mf < 4; mf++) {
                uint32_t ao = (uint32_t)((wm * 64 + mf * 16 + a_r) * KPAD + kk + a_c) * 2;
                uint32_t ah[4], al[4];
                ldsm_x4(ah, stAh + ao);
                ldsm_x4(al, stAl + ao);
#pragma unroll
                for (int nf = 0; nf < 4; nf++) {
                    mma16816(c[mf][nf], ah, bh[nf]);
                    mma16816(c[mf][nf], ah, bl[nf]);
                    mma16816(c[mf][nf], al, bh[nf]);
                }
            }
        }
    }

#pragma unroll
    for (int mf = 0; mf < 4; mf++) {
        int r = m0 + wm * 64 + mf * 16 + g4;
#pragma unroll
        for (int nf = 0; nf < 4; nf++) {
            int cc = n0 + wn * 32 + nf * 8 + cpair;
            *(float2*)(out + (size_t)r * Dn + cc)       = make_float2(c[mf][nf][0], c[mf][nf][1]);
            *(float2*)(out + (size_t)(r + 8) * Dn + cc) = make_float2(c[mf][nf][2], c[mf][nf][3]);
        }
    }
}

// ---------------- beta = sigmoid(x @ Wb + bb) ------------------------------
// R8-measured version (16.4us): 16 tokens/block, smem tiles, 128 blocks.
__global__ void __launch_bounds__(256) beta_kernel(const float* __restrict__ x,
                                                   const float* __restrict__ Wb,
                                                   const float* __restrict__ bbias) {
    __shared__ float sx[16 * 64];
    __shared__ float sW[64 * 16];
    const int tid = threadIdx.x;
    const int tx = tid & 15, ty = tid >> 4;
    const int row0 = blockIdx.x * 16;
    float acc = 0.f;
    for (int k0 = 0; k0 < Dn; k0 += 64) {
        {
            int r = tid >> 4, c4 = (tid & 15) * 4;
            *(float4*)&sx[r * 64 + c4] =
                *(const float4*)&x[(size_t)(row0 + r) * Dn + k0 + c4];
            int wr = tid >> 2, wc4 = (tid & 3) * 4;
            *(float4*)&sW[wr * 16 + wc4] =
                *(const float4*)&Wb[(size_t)(k0 + wr) * Hn + wc4];
        }
        __syncthreads();
#pragma unroll
        for (int kk = 0; kk < 64; kk++)
            acc += sx[ty * 64 + kk] * sW[kk * 16 + tx];
        __syncthreads();
    }
    acc += bbias[tx];
    g_beta[(size_t)(row0 + ty) * Hn + tx] = 1.f / (1.f + expf(-acc));
}

// ---------------- per-chunk state delta: dS = (beta * k/||k||)^T @ v -------
__global__ void __launch_bounds__(256) chunk_delta_kernel() {
    __shared__ float skb[64 * 64];
    __shared__ float sv[64 * 64];
    __shared__ float sbeta[64];
    __shared__ float snorm[64];
    const int c = blockIdx.x, bh = blockIdx.y;
    const int b = bh >> 4, h = bh & 15;
    const int tid = threadIdx.x;
    const int tx = tid & 15, ty = tid >> 4;
    const size_t rowbase = (size_t)b * Ln + c * 64;

#pragma unroll
    for (int r = 0; r < 4; r++) {
        int t = r * 16 + (tid >> 4);
        int e4 = (tid & 15) * 4;
        size_t g = (rowbase + t) * Dn + h * 64 + e4;
        float4 kv = *(const float4*)&g_k[g];
        *(float4*)&skb[t * 64 + e4] = kv;
        *(float4*)&sv[t * 64 + e4] = *(const float4*)&g_v[g];
        float ss = kv.x * kv.x + kv.y * kv.y + kv.z * kv.z + kv.w * kv.w;
        ss += __shfl_xor_sync(0xffffffffu, ss, 1);
        ss += __shfl_xor_sync(0xffffffffu, ss, 2);
        ss += __shfl_xor_sync(0xffffffffu, ss, 4);
        ss += __shfl_xor_sync(0xffffffffu, ss, 8);
        if ((tid & 15) == 0) snorm[t] = ss;
    }
    __syncthreads();
    if (tid < 64)
        sbeta[tid] = g_beta[(rowbase + tid) * Hn + h] /
                     fmaxf(sqrtf(snorm[tid]), 1e-12f);
    __syncthreads();

    float acc[4][4];
#pragma unroll
    for (int i = 0; i < 4; i++)
#pragma unroll
        for (int j = 0; j < 4; j++) acc[i][j] = 0.f;
#pragma unroll 8
    for (int t = 0; t < 64; t++) {
        float4 a = *(const float4*)&skb[t * 64 + ty * 4];
        float s = sbeta[t];
        float4 b4 = *(const float4*)&sv[t * 64 + tx * 4];
        const float af[4] = {a.x * s, a.y * s, a.z * s, a.w * s};
        const float bf[4] = {b4.x, b4.y, b4.z, b4.w};
#pragma unroll
        for (int i = 0; i < 4; i++)
#pragma unroll
            for (int j = 0; j < 4; j++) acc[i][j] += af[i] * bf[j];
    }
    const size_t sbase = ((size_t)bh * NCn + c) * 4096;
#pragma unroll
    for (int i = 0; i < 4; i++)
        *(float4*)&g_sdelta[sbase + (ty * 4 + i) * 64 + tx * 4] =
            make_float4(acc[i][0], acc[i][1], acc[i][2], acc[i][3]);
}

// ---------------- exclusive prefix over 16 chunk states per (b,h) ----------
__global__ void __launch_bounds__(256) prefix_kernel() {
    const int bh = blockIdx.x;
    const int off = blockIdx.y * 1024 + threadIdx.x * 4;
    float4 acc = make_float4(0.f, 0.f, 0.f, 0.f);
    for (int c = 0; c < NCn; c++) {
        size_t base = ((size_t)bh * NCn + c) * 4096 + off;
        *(float4*)&g_sprefix[base] = acc;
        float4 d = *(const float4*)&g_sdelta[base];
        acc.x += d.x; acc.y += d.y; acc.z += d.z; acc.w += d.w;
    }
}

// ---------------- per-chunk output ----------------------------------------
// out = qn @ S_prev + tril(qn kn^T) * beta @ v ; q,k norms fused in.
__global__ void __launch_bounds__(256) chunk_out_kernel() {
    extern __shared__ float smf[];
    float* sqT = smf;             // [64][65] transposed raw q
    float* sX  = smf + 4160;      // multi-use
    float* sA  = smf + 8320;      // [64][64] A^T
    float* sbeta = smf + 12416;   // [64]
    float* sqn = smf + 12480;     // [64] ||q||^2
    float* skn = smf + 12544;     // [64] ||k||^2
    const int c = blockIdx.x, bh = blockIdx.y;
    const int b = bh >> 4, h = bh & 15;
    const int tid = threadIdx.x;
    const int tx = tid & 15, ty = tid >> 4;
    const size_t rowbase = (size_t)b * Ln + c * 64;
    const size_t sbase = ((size_t)bh * NCn + c) * 4096;

    if (tid < 64) sbeta[tid] = g_beta[(rowbase + tid) * Hn + h];
#pragma unroll
    for (int r = 0; r < 4; r++) {
        int t = r * 16 + (tid >> 4);
        int d4 = (tid & 15) * 4;
        float4 qv = *(const float4*)&g_q[(rowbase + t) * Dn + h * 64 + d4];
        sqT[(d4 + 0) * 65 + t] = qv.x;
        sqT[(d4 + 1) * 65 + t] = qv.y;
        sqT[(d4 + 2) * 65 + t] = qv.z;
        sqT[(d4 + 3) * 65 + t] = qv.w;
        float ss = qv.x * qv.x + qv.y * qv.y + qv.z * qv.z + qv.w * qv.w;
        ss += __shfl_xor_sync(0xffffffffu, ss, 1);
        ss += __shfl_xor_sync(0xffffffffu, ss, 2);
        ss += __shfl_xor_sync(0xffffffffu, ss, 4);
        ss += __shfl_xor_sync(0xffffffffu, ss, 8);
        if ((tid & 15) == 0) sqn[t] = ss;
    }
#pragma unroll
    for (int r = 0; r < 4; r++) {
        int idx = r * 1024 + tid * 4;
        *(float4*)&sX[idx] = *(const float4*)&g_sprefix[sbase + idx];
    }
    __syncthreads();

    float acc[4][4];
#pragma unroll
    for (int i = 0; i < 4; i++)
#pragma unroll
        for (int j = 0; j < 4; j++) acc[i][j] = 0.f;

    // phase 1: acc = q_raw @ S_prev  (1/||q|| applied at final write)
#pragma unroll 8
    for (int d = 0; d < 64; d++) {
        float a0 = sqT[d * 65 + ty * 4 + 0];
        float a1 = sqT[d * 65 + ty * 4 + 1];
        float a2v = sqT[d * 65 + ty * 4 + 2];
        float a3 = sqT[d * 65 + ty * 4 + 3];
        float4 bv = *(const float4*)&sX[d * 64 + tx * 4];
        acc[0][0] += a0 * bv.x; acc[0][1] += a0 * bv.y; acc[0][2] += a0 * bv.z; acc[0][3] += a0 * bv.w;
        acc[1][0] += a1 * bv.x; acc[1][1] += a1 * bv.y; acc[1][2] += a1 * bv.z; acc[1][3] += a1 * bv.w;
        acc[2][0] += a2v * bv.x; acc[2][1] += a2v * bv.y; acc[2][2] += a2v * bv.z; acc[2][3] += a2v * bv.w;
        acc[3][0] += a3 * bv.x; acc[3][1] += a3 * bv.y; acc[3][2] += a3 * bv.z; acc[3][3] += a3 * bv.w;
    }
    __syncthreads();
    // load k transposed into sX + row sumsq
#pragma unroll
    for (int r = 0; r < 4; r++) {
        int t = r * 16 + (tid >> 4);
        int d4 = (tid & 15) * 4;
        float4 kv = *(const float4*)&g_k[(rowbase + t) * Dn + h * 64 + d4];
        sX[(d4 + 0) * 65 + t] = kv.x;
        sX[(d4 + 1) * 65 + t] = kv.y;
        sX[(d4 + 2) * 65 + t] = kv.z;
        sX[(d4 + 3) * 65 + t] = kv.w;
        float ss = kv.x * kv.x + kv.y * kv.y + kv.z * kv.z + kv.w * kv.w;
        ss += __shfl_xor_sync(0xffffffffu, ss, 1);
        ss += __shfl_xor_sync(0xffffffffu, ss, 2);
        ss += __shfl_xor_sync(0xffffffffu, ss, 4);
        ss += __shfl_xor_sync(0xffffffffu, ss, 8);
        if ((tid & 15) == 0) skn[t] = ss;
    }
    __syncthreads();

    // phase 2: A[t][s] = q_t.k_s (raw); mask s<=t; scale beta[s]/||k_s||; store A^T
    float a2[4][4];
#pragma unroll
    for (int i = 0; i < 4; i++)
#pragma unroll
        for (int j = 0; j < 4; j++) a2[i][j] = 0.f;
#pragma unroll 8
    for (int d = 0; d < 64; d++) {
        float af[4], bf[4];
#pragma unroll
        for (int i = 0; i < 4; i++) af[i] = sqT[d * 65 + ty * 4 + i];
#pragma unroll
        for (int j = 0; j < 4; j++) bf[j] = sX[d * 65 + tx * 4 + j];
#pragma unroll
        for (int i = 0; i < 4; i++)
#pragma unroll
            for (int j = 0; j < 4; j++) a2[i][j] += af[i] * bf[j];
    }
#pragma unroll
    for (int j = 0; j < 4; j++) {
        int s = tx * 4 + j;
        float bscale = sbeta[s] / fmaxf(sqrtf(skn[s]), 1e-12f);
        float4 v4;
        v4.x = (s <= ty * 4 + 0) ? a2[0][j] * bscale : 0.f;
        v4.y = (s <= ty * 4 + 1) ? a2[1][j] * bscale : 0.f;
        v4.z = (s <= ty * 4 + 2) ? a2[2][j] * bscale : 0.f;
        v4.w = (s <= ty * 4 + 3) ? a2[3][j] * bscale : 0.f;
        *(float4*)&sA[s * 64 + ty * 4] = v4;
    }
    __syncthreads();
#pragma unroll
    for (int r = 0; r < 4; r++) {
        int t = r * 16 + (tid >> 4);
        int e4 = (tid & 15) * 4;
        *(float4*)&sX[t * 64 + e4] =
            *(const float4*)&g_v[(rowbase + t) * Dn + h * 64 + e4];
    }
    __syncthreads();

    // phase 3: acc += A @ v
#pragma unroll 8
    for (int s = 0; s < 64; s++) {
        float4 av = *(const float4*)&sA[s * 64 + ty * 4];
        float4 bv = *(const float4*)&sX[s * 64 + tx * 4];
        const float af[4] = {av.x, av.y, av.z, av.w};
        const float bf[4] = {bv.x, bv.y, bv.z, bv.w};
#pragma unroll
        for (int i = 0; i < 4; i++)
#pragma unroll
            for (int j = 0; j < 4; j++) acc[i][j] += af[i] * bf[j];
    }
    // write attn (scaled by 1/||q_t||) as bf16 hi/lo
#pragma unroll
    for (int i = 0; i < 4; i++) {
        int t = ty * 4 + i;
        float inq = 1.f / fmaxf(sqrtf(sqn[t]), 1e-12f);
        size_t base = (rowbase + t) * Dn + h * 64 + tx * 4;
        __nv_bfloat16 hh[4], ll[4];
#pragma unroll
        for (int j = 0; j < 4; j++) split_hl(acc[i][j] * inq, hh[j], ll[j]);
        __nv_bfloat162 h01, h23, l01, l23;
        h01.x = hh[0]; h01.y = hh[1]; h23.x = hh[2]; h23.y = hh[3];
        l01.x = ll[0]; l01.y = ll[1]; l23.x = ll[2]; l23.y = ll[3];
        *(__nv_bfloat162*)(g_ah + base)     = h01;
        *(__nv_bfloat162*)(g_ah + base + 2) = h23;
        *(__nv_bfloat162*)(g_al + base)     = l01;
        *(__nv_bfloat162*)(g_al + base + 2) = l23;
    }
}

// ---------------------------------------------------------------------------
extern "C" void kernel_launch(void* const* d_in, const int* in_sizes, int n_in,
                              void* d_out, int out_size) {
    const float* x  = (const float*)d_in[0];
    const float* Wq = (const float*)d_in[1];
    const float* Wk = (const float*)d_in[2];
    const float* Wv = (const float*)d_in[3];
    const float* Wo = (const float*)d_in[4];
    const float* Wb = (const float*)d_in[5];
    const float* bb = (const float*)d_in[6];
    float* out = (float*)d_out;

    cudaFuncSetAttribute(mm_qkv_kernel,
                         cudaFuncAttributeMaxDynamicSharedMemorySize, MM16_SMEM_B);
    cudaFuncSetAttribute(mm_out_kernel,
                         cudaFuncAttributeMaxDynamicSharedMemorySize, MM_SMEM_B);
    cudaFuncSetAttribute(chunk_out_kernel,
                         cudaFuncAttributeMaxDynamicSharedMemorySize, 12608 * 4);

    // operand conversion: x -> fp16; W^T: q/k/v fp16, Wo bf16 hi/lo
    convert_x_kernel<<<NT * Dn / 1024, 256>>>(x);
    convert_w_kernel<<<dim3(32, 32, 4), dim3(32, 8)>>>(Wq, Wk, Wv, Wo);
    // gates (before mm_qkv so mm_qkv lands in the ncu capture slot)
    beta_kernel<<<NT / 16, 256>>>(x, Wb, bb);
    // q,k,v projections on tensor cores (single-term fp16)
    mm_qkv_kernel<<<dim3(Dn / 128, NT / 128, 3), 256, MM16_SMEM_B>>>();
    // chunk-local state deltas (k-norm fused)
    chunk_delta_kernel<<<dim3(NCn, BHn), 256>>>();
    // exclusive prefix over chunk states
    prefix_kernel<<<dim3(BHn, 4), 256>>>();
    // per-chunk outputs (q/k-norm fused; writes attn bf16 hi/lo)
    chunk_out_kernel<<<dim3(NCn, BHn), 256, 12608 * 4>>>();
    // final projection on tensor cores (3-term bf16)
    mm_out_kernel<<<dim3(Dn / 128, NT / 128), 256, MM_SMEM_B>>>(out);
}